// round 12
// baseline (speedup 1.0000x reference)
#include <cuda_runtime.h>
#include <cuda_fp16.h>
#include <cstdint>

#define NTOK 4096
#define DIM  1024
#define NEXP 8
#define HID  4096
#define THR  0.3f

#define BM 128
#define BN 256

// ---------------- scratch (static device memory; no allocs anywhere) ----------------
__device__ float g_c[NTOK * NEXP];
__device__ int   g_idx[NEXP][NTOK];
__device__ float g_wt[NEXP][NTOK];
__device__ int   g_cnt[NEXP];
// fp16 A operands in m16n8k16 fragment layout (one uint4 per lane per 16-row x 16-k block)
__device__ __align__(16) uint32_t g_af[(size_t)NEXP * NTOK * DIM / 2];   // half2 units
__device__ __align__(16) uint32_t g_hf[(size_t)NEXP * NTOK * HID / 2];   // half2 units
// fp16 B operands in fragment layout: uint2 per lane per (kt, n-group-of-8)
__device__ __align__(16) uint2 g_wf1[(size_t)NEXP * (DIM / 16) * (HID / 8) * 32];
__device__ __align__(16) uint2 g_wf2[(size_t)NEXP * (HID / 16) * (DIM / 8) * 32];

// ---------------- helpers ----------------
__device__ __forceinline__ uint32_t pack2(float lo, float hi) {
    uint32_t r;
    asm("cvt.rn.f16x2.f32 %0, %1, %2;" : "=r"(r) : "f"(hi), "f"(lo));
    return r;
}

__device__ __forceinline__ void mma16(float* c, const uint4& a, const uint2& b) {
    asm volatile(
        "mma.sync.aligned.m16n8k16.row.col.f32.f16.f16.f32 "
        "{%0,%1,%2,%3}, {%4,%5,%6,%7}, {%8,%9}, {%0,%1,%2,%3};"
        : "+f"(c[0]), "+f"(c[1]), "+f"(c[2]), "+f"(c[3])
        : "r"(a.x), "r"(a.y), "r"(a.z), "r"(a.w), "r"(b.x), "r"(b.y));
}

__device__ __forceinline__ void red_add_v2(float* p, float v0, float v1) {
    asm volatile("red.global.add.v2.f32 [%0], {%1, %2};"
                 :: "l"(p), "f"(v0), "f"(v1) : "memory");
}

__device__ __forceinline__ float gelu_exact(float v) {
    return 0.5f * v * (1.0f + erff(v * 0.70710678118654752f));
}

// ---------------- kernel 1: gate scores, combine weights, out init with sum(c*b2) ----------------
__global__ __launch_bounds__(256) void gate_kernel(
    const float* __restrict__ x, const float* __restrict__ wg,
    const float* __restrict__ bg, const float* __restrict__ b2,
    float* __restrict__ out)
{
    __shared__ float wgs[DIM * 9];
    int tid = threadIdx.x;
    for (int i = tid; i < DIM * NEXP; i += 256)
        wgs[(i >> 3) * 9 + (i & 7)] = wg[i];
    __syncthreads();

    int lane = tid & 31, wid = tid >> 5;
    int n = blockIdx.x * 8 + wid;

    float s[NEXP];
#pragma unroll
    for (int e = 0; e < NEXP; e++) s[e] = 0.f;

    const float* xr = x + (size_t)n * DIM;
    for (int k = lane; k < DIM; k += 32) {
        float xv = xr[k];
#pragma unroll
        for (int e = 0; e < NEXP; e++) s[e] += xv * wgs[k * 9 + e];
    }
#pragma unroll
    for (int e = 0; e < NEXP; e++)
#pragma unroll
        for (int o = 16; o; o >>= 1)
            s[e] += __shfl_xor_sync(0xffffffffu, s[e], o);

    float mx = -1e30f;
#pragma unroll
    for (int e = 0; e < NEXP; e++) { s[e] += bg[e]; mx = fmaxf(mx, s[e]); }
    float sum = 0.f;
#pragma unroll
    for (int e = 0; e < NEXP; e++) { s[e] = expf(s[e] - mx); sum += s[e]; }
    float inv = 1.f / sum;
#pragma unroll
    for (int e = 0; e < NEXP; e++) s[e] *= inv;

    if (lane == 0) {
        float* gs = out + (size_t)NTOK * DIM + (size_t)n * NEXP;
#pragma unroll
        for (int e = 0; e < NEXP; e++) gs[e] = s[e];
    }

    float msum = 0.f; int cnt = 0;
#pragma unroll
    for (int e = 0; e < NEXP; e++) if (s[e] >= THR) { msum += s[e]; cnt++; }
    int top1 = 0; float best = s[0];
#pragma unroll
    for (int e = 1; e < NEXP; e++) if (s[e] > best) { best = s[e]; top1 = e; }
    float dn = 1.f / (msum + 1e-6f);
    float c[NEXP];
#pragma unroll
    for (int e = 0; e < NEXP; e++)
        c[e] = cnt ? ((s[e] >= THR) ? s[e] * dn : 0.f) : ((e == top1) ? 1.f : 0.f);

    if (lane == 0) {
#pragma unroll
        for (int e = 0; e < NEXP; e++) g_c[n * NEXP + e] = c[e];
    }

    for (int d = lane; d < DIM; d += 32) {
        float a = 0.f;
#pragma unroll
        for (int e = 0; e < NEXP; e++) a += c[e] * b2[e * DIM + d];
        out[(size_t)n * DIM + d] = a;
    }
}

// ---------------- kernel 2: per-expert compaction, 1 CTA per expert, 2 barriers ----------------
__global__ __launch_bounds__(256) void compact_kernel()
{
    const int e = blockIdx.x;
    const int tid = threadIdx.x, lane = tid & 31, wid = tid >> 5;
    __shared__ unsigned masks[8][16];
    __shared__ int wbase[8];

    const int base0 = wid * 512;
    int cnt = 0;
#pragma unroll
    for (int i = 0; i < 16; i++) {
        int n = base0 + i * 32 + lane;
        float c = g_c[n * NEXP + e];
        unsigned m = __ballot_sync(0xffffffffu, c > 0.f);
        if (lane == 0) masks[wid][i] = m;
        cnt += __popc(m);
    }
    __shared__ int wcnt[8];
    if (lane == 0) wcnt[wid] = cnt;
    __syncthreads();
    if (tid == 0) {
        int acc = 0;
#pragma unroll
        for (int w = 0; w < 8; w++) { wbase[w] = acc; acc += wcnt[w]; }
        g_cnt[e] = acc;
    }
    __syncthreads();

    int pos = wbase[wid];
#pragma unroll
    for (int i = 0; i < 16; i++) {
        unsigned m = masks[wid][i];
        if ((m >> lane) & 1u) {
            int n = base0 + i * 32 + lane;
            int p = pos + __popc(m & ((1u << lane) - 1u));
            g_idx[e][p] = n;
            g_wt[e][p]  = g_c[n * NEXP + e];
        }
        pos += __popc(m);
    }
}

// ---------------- kernel 2b: gather + fp16-round expert inputs into fragment layout ----------------
__global__ __launch_bounds__(256) void permA_kernel(const float* __restrict__ ei)
{
    const int st = blockIdx.x;
    const int e  = blockIdx.y;
    const int me = g_cnt[e];
    if (st * BM >= me) return;
    const int tid = threadIdx.x;
    uint4* dst = (uint4*)g_af;

#pragma unroll 2
    for (int i = 0; i < 64; i++) {
        int idx  = i * 256 + tid;
        int lane = idx & 31;
        int kq   = (idx >> 5) & 63;
        int rr   = idx >> 11;
        int g = lane >> 2, t = lane & 3;
        int r = rr * 16 + g;
        int s0 = st * BM + r, s1 = s0 + 8;
        int tok0 = (s0 < me) ? g_idx[e][s0] : 0;
        int tok1 = (s1 < me) ? g_idx[e][s1] : 0;
        const float2* r0 = (const float2*)(ei + ((size_t)e * NTOK + tok0) * DIM);
        const float2* r1 = (const float2*)(ei + ((size_t)e * NTOK + tok1) * DIM);
        float2 a00 = r0[kq * 8 + t];
        float2 a01 = r0[kq * 8 + t + 4];
        float2 a10 = r1[kq * 8 + t];
        float2 a11 = r1[kq * 8 + t + 4];
        uint4 v;
        v.x = pack2(a00.x, a00.y);
        v.y = pack2(a10.x, a10.y);
        v.z = pack2(a01.x, a01.y);
        v.w = pack2(a11.x, a11.y);
        dst[(((size_t)(e * 32 + st) * 64 + kq) * 8 + rr) * 32 + lane] = v;
    }
}

// ---------------- kernel 2c: weights -> fp16 B-fragment layout ----------------
__global__ __launch_bounds__(256) void permW_kernel(
    const float* __restrict__ w, uint2* __restrict__ wf, int K, int N)
{
    const int kt = blockIdx.x;
    const int nb = blockIdx.y;
    const int e  = blockIdx.z;
    __shared__ float s[16][132];
    const float* wp = w + (size_t)e * K * N + (size_t)kt * 16 * N + nb * 128;
    const int tid = threadIdx.x;

#pragma unroll
    for (int i = 0; i < 2; i++) {
        int idx = tid + i * 256;
        int row = idx >> 5, c4 = (idx & 31) * 4;
        float4 v = *(const float4*)(wp + (size_t)row * N + c4);
        s[row][c4 + 0] = v.x; s[row][c4 + 1] = v.y;
        s[row][c4 + 2] = v.z; s[row][c4 + 3] = v.w;
    }
    __syncthreads();

    const int NG = N / 8;
    uint2* dst = wf + (((size_t)e * (K / 16) + kt) * NG + nb * 16) * 32;
#pragma unroll
    for (int i = 0; i < 2; i++) {
        int u = tid + i * 256;
        int k2 = u & 3, c8 = (u >> 2) & 7, Gl = u >> 5;
        int n = Gl * 8 + c8;
        uint2 o;
        o.x = pack2(s[2 * k2][n],     s[2 * k2 + 1][n]);
        o.y = pack2(s[2 * k2 + 8][n], s[2 * k2 + 9][n]);
        dst[(size_t)Gl * 32 + c8 * 4 + k2] = o;
    }
}

// =====================================================================================
// FFN GEMMs: 8 warps/CTA (2 wm x 4 wn of 64x64 warp tiles), CTA 128x256, fp16 MMA.
// NO smem, NO barriers: A and B direct fragment LDGs, register double-buffered.
// Per-warp instruction stream identical to the 4-warp variant; packaging halves
// the A-operand L2 re-read factor.
// =====================================================================================

// ---------------- kernel 3: grouped GEMM1: g_hf = frag16(gelu(A @ wf1 + b1)) ----------------
__global__ __launch_bounds__(256, 1) void ffn1_kernel(const float* __restrict__ b1)
{
    const int e  = blockIdx.z;
    const int me = g_cnt[e];
    const int mt = blockIdx.x;
    if (mt * BM >= me) return;
    const int n0 = blockIdx.y * BN;

    const int tid  = threadIdx.x;
    const int lane = tid & 31;
    const int wid  = tid >> 5;
    const int wm   = wid >> 2;     // 0..1
    const int wn   = wid & 3;      // 0..3
    const int g    = lane >> 2;
    const int t    = lane & 3;

    const uint4* aF = (const uint4*)g_af;
    const size_t aB = (size_t)(e * 32 + mt) * 64 * 256 + (wm * 4) * 32 + lane;
    const uint2* bW = g_wf1 + (size_t)e * 64 * 512 * 32
                    + ((size_t)(n0 >> 3) + wn * 8) * 32 + lane;

    float acc[4][8][4];
#pragma unroll
    for (int a = 0; a < 4; a++)
#pragma unroll
        for (int b = 0; b < 8; b++)
#pragma unroll
            for (int q = 0; q < 4; q++) acc[a][b][q] = 0.f;

    uint4 a0[4], a1[4];
    uint2 b0[8], b1r[8];

#pragma unroll
    for (int mi = 0; mi < 4; mi++) a0[mi] = aF[aB + mi * 32];
#pragma unroll
    for (int ni = 0; ni < 8; ni++) b0[ni] = bW[ni * 32];

    const int KT = DIM / 16;   // 64
    for (int kt = 0; kt < KT; kt += 2) {
#pragma unroll
        for (int mi = 0; mi < 4; mi++)
            a1[mi] = aF[aB + (size_t)(kt + 1) * 256 + mi * 32];
#pragma unroll
        for (int ni = 0; ni < 8; ni++)
            b1r[ni] = bW[(size_t)(kt + 1) * 16384 + ni * 32];
#pragma unroll
        for (int ni = 0; ni < 8; ni++)
#pragma unroll
            for (int mi = 0; mi < 4; mi++)
                mma16(acc[mi][ni], a0[mi], b0[ni]);
        if (kt + 2 < KT) {
#pragma unroll
            for (int mi = 0; mi < 4; mi++)
                a0[mi] = aF[aB + (size_t)(kt + 2) * 256 + mi * 32];
#pragma unroll
            for (int ni = 0; ni < 8; ni++)
                b0[ni] = bW[(size_t)(kt + 2) * 16384 + ni * 32];
        }
#pragma unroll
        for (int ni = 0; ni < 8; ni++)
#pragma unroll
            for (int mi = 0; mi < 4; mi++)
                mma16(acc[mi][ni], a1[mi], b1r[ni]);
    }

    // epilogue: +b1, exact GELU, pack to fp16 fragment layout for GEMM2
    float bv[8][2];
#pragma unroll
    for (int ni = 0; ni < 8; ni++) {
        int c = n0 + wn * 64 + ni * 8 + 2 * t;
        bv[ni][0] = b1[e * HID + c];
        bv[ni][1] = b1[e * HID + c + 1];
    }
    uint4* hf = (uint4*)g_hf;
#pragma unroll
    for (int mi = 0; mi < 4; mi++) {
#pragma unroll
        for (int p = 0; p < 4; p++) {
            int n0i = 2 * p, n1i = 2 * p + 1;
            uint4 v;
            v.x = pack2(gelu_exact(acc[mi][n0i][0] + bv[n0i][0]),
                        gelu_exact(acc[mi][n0i][1] + bv[n0i][1]));
            v.y = pack2(gelu_exact(acc[mi][n0i][2] + bv[n0i][0]),
                        gelu_exact(acc[mi][n0i][3] + bv[n0i][1]));
            v.z = pack2(gelu_exact(acc[mi][n1i][0] + bv[n1i][0]),
                        gelu_exact(acc[mi][n1i][1] + bv[n1i][1]));
            v.w = pack2(gelu_exact(acc[mi][n1i][2] + bv[n1i][0]),
                        gelu_exact(acc[mi][n1i][3] + bv[n1i][1]));
            int kq = (n0 >> 4) + wn * 4 + p;
            hf[(((size_t)(e * 32 + mt) * 256 + kq) * 8 + (wm * 4 + mi)) * 32 + lane] = v;
        }
    }
}

// ---------------- kernel 4: grouped GEMM2 (K-split x2): out[tok] += c * (g_hf @ wf2) ----------------
__global__ __launch_bounds__(256, 1) void ffn2_kernel(float* __restrict__ out)
{
    const int e  = blockIdx.z >> 1;
    const int sp = blockIdx.z & 1;
    const int me = g_cnt[e];
    const int mt = blockIdx.x;
    if (mt * BM >= me) return;
    const int n0 = blockIdx.y * BN;

    const int tid  = threadIdx.x;
    const int lane = tid & 31;
    const int wid  = tid >> 5;
    const int wm   = wid >> 2;
    const int wn   = wid & 3;
    const int g    = lane >> 2;
    const int t    = lane & 3;

    const uint4* aF = (const uint4*)g_hf;
    const size_t aB = (size_t)(e * 32 + mt) * 256 * 256 + (size_t)(sp * 128) * 256
                    + (wm * 4) * 32 + lane;
    // B fragments: NG = DIM/8 = 128 -> per kt stride = 128*32 = 4096 uint2
    const uint2* bW = g_wf2 + (size_t)e * 256 * 128 * 32 + (size_t)(sp * 128) * 4096
                    + ((size_t)(n0 >> 3) + wn * 8) * 32 + lane;

    float acc[4][8][4];
#pragma unroll
    for (int a = 0; a < 4; a++)
#pragma unroll
        for (int b = 0; b < 8; b++)
#pragma unroll
            for (int q = 0; q < 4; q++) acc[a][b][q] = 0.f;

    uint4 a0[4], a1[4];
    uint2 b0[8], b1r[8];

#pragma unroll
    for (int mi = 0; mi < 4; mi++) a0[mi] = aF[aB + mi * 32];
#pragma unroll
    for (int ni = 0; ni < 8; ni++) b0[ni] = bW[ni * 32];

    const int KT = (HID / 2) / 16;   // 128 per split
    for (int kt = 0; kt < KT; kt += 2) {
#pragma unroll
        for (int mi = 0; mi < 4; mi++)
            a1[mi] = aF[aB + (size_t)(kt + 1) * 256 + mi * 32];
#pragma unroll
        for (int ni = 0; ni < 8; ni++)
            b1r[ni] = bW[(size_t)(kt + 1) * 4096 + ni * 32];
#pragma unroll
        for (int ni = 0; ni < 8; ni++)
#pragma unroll
            for (int mi = 0; mi < 4; mi++)
                mma16(acc[mi][ni], a0[mi], b0[ni]);
        if (kt + 2 < KT) {
#pragma unroll
            for (int mi = 0; mi < 4; mi++)
                a0[mi] = aF[aB + (size_t)(kt + 2) * 256 + mi * 32];
#pragma unroll
            for (int ni = 0; ni < 8; ni++)
                b0[ni] = bW[(size_t)(kt + 2) * 4096 + ni * 32];
        }
#pragma unroll
        for (int ni = 0; ni < 8; ni++)
#pragma unroll
            for (int mi = 0; mi < 4; mi++)
                mma16(acc[mi][ni], a1[mi], b1r[ni]);
    }

    // epilogue: scaled vector scatter-add (red.global.add.v2.f32); split partials add
#pragma unroll
    for (int mi = 0; mi < 4; mi++) {
#pragma unroll
        for (int h2 = 0; h2 < 2; h2++) {
            int row = wm * 64 + mi * 16 + g + 8 * h2;
            int ss = mt * BM + row;
            if (ss < me) {
                int tok  = g_idx[e][ss];
                float wc = g_wt[e][ss];
                float* orow = out + (size_t)tok * DIM;
#pragma unroll
                for (int ni = 0; ni < 8; ni++) {
                    int col = n0 + wn * 64 + ni * 8 + 2 * t;
                    red_add_v2(orow + col,
                               wc * acc[mi][ni][2 * h2 + 0],
                               wc * acc[mi][ni][2 * h2 + 1]);
                }
            }
        }
    }
}

// ---------------- launch ----------------
extern "C" void kernel_launch(void* const* d_in, const int* in_sizes, int n_in,
                              void* d_out, int out_size)
{
    (void)in_sizes; (void)n_in; (void)out_size;
    const float* x  = (const float*)d_in[0];
    const float* ei = (const float*)d_in[1];
    const float* wg = (const float*)d_in[2];
    const float* bg = (const float*)d_in[3];
    const float* w1 = (const float*)d_in[4];
    const float* b1 = (const float*)d_in[5];
    const float* w2 = (const float*)d_in[6];
    const float* b2 = (const float*)d_in[7];
    float* out = (float*)d_out;

    uint2* wf1; cudaGetSymbolAddress((void**)&wf1, g_wf1);
    uint2* wf2; cudaGetSymbolAddress((void**)&wf2, g_wf2);

    // lazily-created side stream + events (resource setup only; captured work is
    // identical on every call -> deterministic graph)
    static cudaStream_t s_aux = nullptr;
    static cudaEvent_t ev_fork = nullptr, ev_w1 = nullptr, ev_w2 = nullptr;
    if (!s_aux) {
        cudaStreamCreateWithFlags(&s_aux, cudaStreamNonBlocking);
        cudaEventCreateWithFlags(&ev_fork, cudaEventDisableTiming);
        cudaEventCreateWithFlags(&ev_w1, cudaEventDisableTiming);
        cudaEventCreateWithFlags(&ev_w2, cudaEventDisableTiming);
    }

    // fork: weight permutation on side stream; per-GEMM joins keep permW2 off
    // ffn1's critical path (it overlaps ffn1 execution instead)
    cudaEventRecord(ev_fork, 0);
    cudaStreamWaitEvent(s_aux, ev_fork, 0);
    permW_kernel<<<dim3(DIM / 16, HID / 128, NEXP), 256, 0, s_aux>>>(w1, wf1, DIM, HID);
    cudaEventRecord(ev_w1, s_aux);
    permW_kernel<<<dim3(HID / 16, DIM / 128, NEXP), 256, 0, s_aux>>>(w2, wf2, HID, DIM);
    cudaEventRecord(ev_w2, s_aux);

    gate_kernel<<<NTOK / 8, 256>>>(x, wg, bg, b2, out);
    compact_kernel<<<NEXP, 256>>>();
    permA_kernel<<<dim3(NTOK / BM, NEXP), 256>>>(ei);

    cudaStreamWaitEvent(0, ev_w1, 0);
    ffn1_kernel<<<dim3(NTOK / BM, HID / BN, NEXP), 256>>>(b1);
    cudaStreamWaitEvent(0, ev_w2, 0);
    ffn2_kernel<<<dim3(NTOK / BM, DIM / BN, NEXP * 2), 256>>>(out);
}

// round 13
// speedup vs baseline: 1.0382x; 1.0382x over previous
#include <cuda_runtime.h>
#include <cuda_fp16.h>
#include <cstdint>

#define NTOK 4096
#define DIM  1024
#define NEXP 8
#define HID  4096
#define THR  0.3f

#define BM 128
#define BN 128

// ---------------- scratch (static device memory; no allocs anywhere) ----------------
__device__ float g_c[NTOK * NEXP];
__device__ int   g_idx[NEXP][NTOK];
__device__ float g_wt[NEXP][NTOK];
__device__ int   g_cnt[NEXP];
// fp16 A operands in m16n8k16 fragment layout (one uint4 per lane per 16-row x 16-k block)
__device__ __align__(16) uint32_t g_af[(size_t)NEXP * NTOK * DIM / 2];   // half2 units
__device__ __align__(16) uint32_t g_hf[(size_t)NEXP * NTOK * HID / 2];   // half2 units
// fp16 B operands in fragment layout: uint2 per lane per (kt, n-group-of-8)
__device__ __align__(16) uint2 g_wf1[(size_t)NEXP * (DIM / 16) * (HID / 8) * 32];
__device__ __align__(16) uint2 g_wf2[(size_t)NEXP * (HID / 16) * (DIM / 8) * 32];

// ---------------- helpers ----------------
__device__ __forceinline__ uint32_t pack2(float lo, float hi) {
    uint32_t r;
    asm("cvt.rn.f16x2.f32 %0, %1, %2;" : "=r"(r) : "f"(hi), "f"(lo));
    return r;
}

__device__ __forceinline__ void mma16(float* c, const uint4& a, const uint2& b) {
    asm volatile(
        "mma.sync.aligned.m16n8k16.row.col.f32.f16.f16.f32 "
        "{%0,%1,%2,%3}, {%4,%5,%6,%7}, {%8,%9}, {%0,%1,%2,%3};"
        : "+f"(c[0]), "+f"(c[1]), "+f"(c[2]), "+f"(c[3])
        : "r"(a.x), "r"(a.y), "r"(a.z), "r"(a.w), "r"(b.x), "r"(b.y));
}

__device__ __forceinline__ void red_add_v2(float* p, float v0, float v1) {
    asm volatile("red.global.add.v2.f32 [%0], {%1, %2};"
                 :: "l"(p), "f"(v0), "f"(v1) : "memory");
}

__device__ __forceinline__ float gelu_exact(float v) {
    return 0.5f * v * (1.0f + erff(v * 0.70710678118654752f));
}

// ---------------- kernel 1: gate scores, combine weights, out init with sum(c*b2) ----------------
__global__ __launch_bounds__(256) void gate_kernel(
    const float* __restrict__ x, const float* __restrict__ wg,
    const float* __restrict__ bg, const float* __restrict__ b2,
    float* __restrict__ out)
{
    __shared__ float wgs[DIM * 9];
    int tid = threadIdx.x;
    for (int i = tid; i < DIM * NEXP; i += 256)
        wgs[(i >> 3) * 9 + (i & 7)] = wg[i];
    __syncthreads();

    int lane = tid & 31, wid = tid >> 5;
    int n = blockIdx.x * 8 + wid;

    float s[NEXP];
#pragma unroll
    for (int e = 0; e < NEXP; e++) s[e] = 0.f;

    const float* xr = x + (size_t)n * DIM;
    for (int k = lane; k < DIM; k += 32) {
        float xv = xr[k];
#pragma unroll
        for (int e = 0; e < NEXP; e++) s[e] += xv * wgs[k * 9 + e];
    }
#pragma unroll
    for (int e = 0; e < NEXP; e++)
#pragma unroll
        for (int o = 16; o; o >>= 1)
            s[e] += __shfl_xor_sync(0xffffffffu, s[e], o);

    float mx = -1e30f;
#pragma unroll
    for (int e = 0; e < NEXP; e++) { s[e] += bg[e]; mx = fmaxf(mx, s[e]); }
    float sum = 0.f;
#pragma unroll
    for (int e = 0; e < NEXP; e++) { s[e] = expf(s[e] - mx); sum += s[e]; }
    float inv = 1.f / sum;
#pragma unroll
    for (int e = 0; e < NEXP; e++) s[e] *= inv;

    if (lane == 0) {
        float* gs = out + (size_t)NTOK * DIM + (size_t)n * NEXP;
#pragma unroll
        for (int e = 0; e < NEXP; e++) gs[e] = s[e];
    }

    float msum = 0.f; int cnt = 0;
#pragma unroll
    for (int e = 0; e < NEXP; e++) if (s[e] >= THR) { msum += s[e]; cnt++; }
    int top1 = 0; float best = s[0];
#pragma unroll
    for (int e = 1; e < NEXP; e++) if (s[e] > best) { best = s[e]; top1 = e; }
    float dn = 1.f / (msum + 1e-6f);
    float c[NEXP];
#pragma unroll
    for (int e = 0; e < NEXP; e++)
        c[e] = cnt ? ((s[e] >= THR) ? s[e] * dn : 0.f) : ((e == top1) ? 1.f : 0.f);

    if (lane == 0) {
#pragma unroll
        for (int e = 0; e < NEXP; e++) g_c[n * NEXP + e] = c[e];
    }

    for (int d = lane; d < DIM; d += 32) {
        float a = 0.f;
#pragma unroll
        for (int e = 0; e < NEXP; e++) a += c[e] * b2[e * DIM + d];
        out[(size_t)n * DIM + d] = a;
    }
}

// ---------------- kernel 2: per-expert compaction, 1 CTA per expert, 2 barriers ----------------
__global__ __launch_bounds__(256) void compact_kernel()
{
    const int e = blockIdx.x;
    const int tid = threadIdx.x, lane = tid & 31, wid = tid >> 5;
    __shared__ unsigned masks[8][16];
    __shared__ int wbase[8];

    const int base0 = wid * 512;
    int cnt = 0;
#pragma unroll
    for (int i = 0; i < 16; i++) {
        int n = base0 + i * 32 + lane;
        float c = g_c[n * NEXP + e];
        unsigned m = __ballot_sync(0xffffffffu, c > 0.f);
        if (lane == 0) masks[wid][i] = m;
        cnt += __popc(m);
    }
    __shared__ int wcnt[8];
    if (lane == 0) wcnt[wid] = cnt;
    __syncthreads();
    if (tid == 0) {
        int acc = 0;
#pragma unroll
        for (int w = 0; w < 8; w++) { wbase[w] = acc; acc += wcnt[w]; }
        g_cnt[e] = acc;
    }
    __syncthreads();

    int pos = wbase[wid];
#pragma unroll
    for (int i = 0; i < 16; i++) {
        unsigned m = masks[wid][i];
        if ((m >> lane) & 1u) {
            int n = base0 + i * 32 + lane;
            int p = pos + __popc(m & ((1u << lane) - 1u));
            g_idx[e][p] = n;
            g_wt[e][p]  = g_c[n * NEXP + e];
        }
        pos += __popc(m);
    }
}

// ---------------- kernel 2b: gather + fp16-round expert inputs into fragment layout ----------------
__global__ __launch_bounds__(256) void permA_kernel(const float* __restrict__ ei)
{
    const int st = blockIdx.x;
    const int e  = blockIdx.y;
    const int me = g_cnt[e];
    if (st * BM >= me) return;
    const int tid = threadIdx.x;
    uint4* dst = (uint4*)g_af;

#pragma unroll 2
    for (int i = 0; i < 64; i++) {
        int idx  = i * 256 + tid;
        int lane = idx & 31;
        int kq   = (idx >> 5) & 63;
        int rr   = idx >> 11;
        int g = lane >> 2, t = lane & 3;
        int r = rr * 16 + g;
        int s0 = st * BM + r, s1 = s0 + 8;
        int tok0 = (s0 < me) ? g_idx[e][s0] : 0;
        int tok1 = (s1 < me) ? g_idx[e][s1] : 0;
        const float2* r0 = (const float2*)(ei + ((size_t)e * NTOK + tok0) * DIM);
        const float2* r1 = (const float2*)(ei + ((size_t)e * NTOK + tok1) * DIM);
        float2 a00 = r0[kq * 8 + t];
        float2 a01 = r0[kq * 8 + t + 4];
        float2 a10 = r1[kq * 8 + t];
        float2 a11 = r1[kq * 8 + t + 4];
        uint4 v;
        v.x = pack2(a00.x, a00.y);
        v.y = pack2(a10.x, a10.y);
        v.z = pack2(a01.x, a01.y);
        v.w = pack2(a11.x, a11.y);
        dst[(((size_t)(e * 32 + st) * 64 + kq) * 8 + rr) * 32 + lane] = v;
    }
}

// ---------------- kernel 2c: weights -> fp16 B-fragment layout ----------------
__global__ __launch_bounds__(256) void permW_kernel(
    const float* __restrict__ w, uint2* __restrict__ wf, int K, int N)
{
    const int kt = blockIdx.x;
    const int nb = blockIdx.y;
    const int e  = blockIdx.z;
    __shared__ float s[16][132];
    const float* wp = w + (size_t)e * K * N + (size_t)kt * 16 * N + nb * 128;
    const int tid = threadIdx.x;

#pragma unroll
    for (int i = 0; i < 2; i++) {
        int idx = tid + i * 256;
        int row = idx >> 5, c4 = (idx & 31) * 4;
        float4 v = *(const float4*)(wp + (size_t)row * N + c4);
        s[row][c4 + 0] = v.x; s[row][c4 + 1] = v.y;
        s[row][c4 + 2] = v.z; s[row][c4 + 3] = v.w;
    }
    __syncthreads();

    const int NG = N / 8;
    uint2* dst = wf + (((size_t)e * (K / 16) + kt) * NG + nb * 16) * 32;
#pragma unroll
    for (int i = 0; i < 2; i++) {
        int u = tid + i * 256;
        int k2 = u & 3, c8 = (u >> 2) & 7, Gl = u >> 5;
        int n = Gl * 8 + c8;
        uint2 o;
        o.x = pack2(s[2 * k2][n],     s[2 * k2 + 1][n]);
        o.y = pack2(s[2 * k2 + 8][n], s[2 * k2 + 9][n]);
        dst[(size_t)Gl * 32 + c8 * 4 + k2] = o;
    }
}

// =====================================================================================
// FFN GEMMs: 4 warps/CTA (2 wm x 2 wn of 64x64 tiles), CTA 128x128, k-step 16, fp16 MMA.
// NO smem, NO barriers: A and B direct fragment LDGs, register double-buffered.
// =====================================================================================

// ---------------- kernel 3: grouped GEMM1: g_hf = frag16(gelu(A @ wf1 + b1)) ----------------
__global__ __launch_bounds__(128, 2) void ffn1_kernel(const float* __restrict__ b1)
{
    const int e  = blockIdx.z;
    const int me = g_cnt[e];
    const int mt = blockIdx.x;
    if (mt * BM >= me) return;
    const int n0 = blockIdx.y * BN;

    const int tid  = threadIdx.x;
    const int lane = tid & 31;
    const int wid  = tid >> 5;
    const int wm   = wid >> 1;
    const int wn   = wid & 1;
    const int g    = lane >> 2;
    const int t    = lane & 3;

    const uint4* aF = (const uint4*)g_af;
    const size_t aB = (size_t)(e * 32 + mt) * 64 * 256 + (wm * 4) * 32 + lane;
    const uint2* bW = g_wf1 + (size_t)e * 64 * 512 * 32
                    + ((size_t)(n0 >> 3) + wn * 8) * 32 + lane;

    float acc[4][8][4];
#pragma unroll
    for (int a = 0; a < 4; a++)
#pragma unroll
        for (int b = 0; b < 8; b++)
#pragma unroll
            for (int q = 0; q < 4; q++) acc[a][b][q] = 0.f;

    uint4 a0[4], a1[4];
    uint2 b0[8], b1r[8];

#pragma unroll
    for (int mi = 0; mi < 4; mi++) a0[mi] = aF[aB + mi * 32];
#pragma unroll
    for (int ni = 0; ni < 8; ni++) b0[ni] = bW[ni * 32];

    const int KT = DIM / 16;   // 64
    for (int kt = 0; kt < KT; kt += 2) {
#pragma unroll
        for (int mi = 0; mi < 4; mi++)
            a1[mi] = aF[aB + (size_t)(kt + 1) * 256 + mi * 32];
#pragma unroll
        for (int ni = 0; ni < 8; ni++)
            b1r[ni] = bW[(size_t)(kt + 1) * 16384 + ni * 32];
#pragma unroll
        for (int ni = 0; ni < 8; ni++)
#pragma unroll
            for (int mi = 0; mi < 4; mi++)
                mma16(acc[mi][ni], a0[mi], b0[ni]);
        if (kt + 2 < KT) {
#pragma unroll
            for (int mi = 0; mi < 4; mi++)
                a0[mi] = aF[aB + (size_t)(kt + 2) * 256 + mi * 32];
#pragma unroll
            for (int ni = 0; ni < 8; ni++)
                b0[ni] = bW[(size_t)(kt + 2) * 16384 + ni * 32];
        }
#pragma unroll
        for (int ni = 0; ni < 8; ni++)
#pragma unroll
            for (int mi = 0; mi < 4; mi++)
                mma16(acc[mi][ni], a1[mi], b1r[ni]);
    }

    // epilogue: +b1, exact GELU, pack to fp16 fragment layout for GEMM2
    float bv[8][2];
#pragma unroll
    for (int ni = 0; ni < 8; ni++) {
        int c = n0 + wn * 64 + ni * 8 + 2 * t;
        bv[ni][0] = b1[e * HID + c];
        bv[ni][1] = b1[e * HID + c + 1];
    }
    uint4* hf = (uint4*)g_hf;
#pragma unroll
    for (int mi = 0; mi < 4; mi++) {
#pragma unroll
        for (int p = 0; p < 4; p++) {
            int n0i = 2 * p, n1i = 2 * p + 1;
            uint4 v;
            v.x = pack2(gelu_exact(acc[mi][n0i][0] + bv[n0i][0]),
                        gelu_exact(acc[mi][n0i][1] + bv[n0i][1]));
            v.y = pack2(gelu_exact(acc[mi][n0i][2] + bv[n0i][0]),
                        gelu_exact(acc[mi][n0i][3] + bv[n0i][1]));
            v.z = pack2(gelu_exact(acc[mi][n1i][0] + bv[n1i][0]),
                        gelu_exact(acc[mi][n1i][1] + bv[n1i][1]));
            v.w = pack2(gelu_exact(acc[mi][n1i][2] + bv[n1i][0]),
                        gelu_exact(acc[mi][n1i][3] + bv[n1i][1]));
            int kq = (n0 >> 4) + wn * 4 + p;
            hf[(((size_t)(e * 32 + mt) * 256 + kq) * 8 + (wm * 4 + mi)) * 32 + lane] = v;
        }
    }
}

// ---------------- kernel 4: grouped GEMM2 (K-split x2): out[tok] += c * (g_hf @ wf2) ----------------
__global__ __launch_bounds__(128, 2) void ffn2_kernel(float* __restrict__ out)
{
    const int e  = blockIdx.z >> 1;
    const int sp = blockIdx.z & 1;
    const int me = g_cnt[e];
    const int mt = blockIdx.x;
    if (mt * BM >= me) return;
    const int n0 = blockIdx.y * BN;

    const int tid  = threadIdx.x;
    const int lane = tid & 31;
    const int wid  = tid >> 5;
    const int wm   = wid >> 1;
    const int wn   = wid & 1;
    const int g    = lane >> 2;
    const int t    = lane & 3;

    const uint4* aF = (const uint4*)g_hf;
    const size_t aB = (size_t)(e * 32 + mt) * 256 * 256 + (size_t)(sp * 128) * 256
                    + (wm * 4) * 32 + lane;
    // B fragments: NG = DIM/8 = 128 -> per kt stride = 128*32 = 4096 uint2
    const uint2* bW = g_wf2 + (size_t)e * 256 * 128 * 32 + (size_t)(sp * 128) * 4096
                    + ((size_t)(n0 >> 3) + wn * 8) * 32 + lane;

    float acc[4][8][4];
#pragma unroll
    for (int a = 0; a < 4; a++)
#pragma unroll
        for (int b = 0; b < 8; b++)
#pragma unroll
            for (int q = 0; q < 4; q++) acc[a][b][q] = 0.f;

    uint4 a0[4], a1[4];
    uint2 b0[8], b1r[8];

#pragma unroll
    for (int mi = 0; mi < 4; mi++) a0[mi] = aF[aB + mi * 32];
#pragma unroll
    for (int ni = 0; ni < 8; ni++) b0[ni] = bW[ni * 32];

    const int KT = (HID / 2) / 16;   // 128 per split
    for (int kt = 0; kt < KT; kt += 2) {
#pragma unroll
        for (int mi = 0; mi < 4; mi++)
            a1[mi] = aF[aB + (size_t)(kt + 1) * 256 + mi * 32];
#pragma unroll
        for (int ni = 0; ni < 8; ni++)
            b1r[ni] = bW[(size_t)(kt + 1) * 4096 + ni * 32];
#pragma unroll
        for (int ni = 0; ni < 8; ni++)
#pragma unroll
            for (int mi = 0; mi < 4; mi++)
                mma16(acc[mi][ni], a0[mi], b0[ni]);
        if (kt + 2 < KT) {
#pragma unroll
            for (int mi = 0; mi < 4; mi++)
                a0[mi] = aF[aB + (size_t)(kt + 2) * 256 + mi * 32];
#pragma unroll
            for (int ni = 0; ni < 8; ni++)
                b0[ni] = bW[(size_t)(kt + 2) * 4096 + ni * 32];
        }
#pragma unroll
        for (int ni = 0; ni < 8; ni++)
#pragma unroll
            for (int mi = 0; mi < 4; mi++)
                mma16(acc[mi][ni], a1[mi], b1r[ni]);
    }

    // epilogue: scaled vector scatter-add (red.global.add.v2.f32); split partials add
#pragma unroll
    for (int mi = 0; mi < 4; mi++) {
#pragma unroll
        for (int h2 = 0; h2 < 2; h2++) {
            int row = wm * 64 + mi * 16 + g + 8 * h2;
            int ss = mt * BM + row;
            if (ss < me) {
                int tok  = g_idx[e][ss];
                float wc = g_wt[e][ss];
                float* orow = out + (size_t)tok * DIM;
#pragma unroll
                for (int ni = 0; ni < 8; ni++) {
                    int col = n0 + wn * 64 + ni * 8 + 2 * t;
                    red_add_v2(orow + col,
                               wc * acc[mi][ni][2 * h2 + 0],
                               wc * acc[mi][ni][2 * h2 + 1]);
                }
            }
        }
    }
}

// ---------------- launch ----------------
extern "C" void kernel_launch(void* const* d_in, const int* in_sizes, int n_in,
                              void* d_out, int out_size)
{
    (void)in_sizes; (void)n_in; (void)out_size;
    const float* x  = (const float*)d_in[0];
    const float* ei = (const float*)d_in[1];
    const float* wg = (const float*)d_in[2];
    const float* bg = (const float*)d_in[3];
    const float* w1 = (const float*)d_in[4];
    const float* b1 = (const float*)d_in[5];
    const float* w2 = (const float*)d_in[6];
    const float* b2 = (const float*)d_in[7];
    float* out = (float*)d_out;

    uint2* wf1; cudaGetSymbolAddress((void**)&wf1, g_wf1);
    uint2* wf2; cudaGetSymbolAddress((void**)&wf2, g_wf2);

    // lazily-created side stream + events (resource setup only; captured work is
    // identical on every call -> deterministic graph)
    static cudaStream_t s_aux = nullptr;
    static cudaEvent_t ev_fork = nullptr, ev_w1 = nullptr, ev_w2 = nullptr;
    if (!s_aux) {
        cudaStreamCreateWithFlags(&s_aux, cudaStreamNonBlocking);
        cudaEventCreateWithFlags(&ev_fork, cudaEventDisableTiming);
        cudaEventCreateWithFlags(&ev_w1, cudaEventDisableTiming);
        cudaEventCreateWithFlags(&ev_w2, cudaEventDisableTiming);
    }

    // fork: weight permutation on side stream; per-GEMM joins keep permW2 off
    // ffn1's critical path (it overlaps ffn1 execution instead)
    cudaEventRecord(ev_fork, 0);
    cudaStreamWaitEvent(s_aux, ev_fork, 0);
    permW_kernel<<<dim3(DIM / 16, HID / 128, NEXP), 256, 0, s_aux>>>(w1, wf1, DIM, HID);
    cudaEventRecord(ev_w1, s_aux);
    permW_kernel<<<dim3(HID / 16, DIM / 128, NEXP), 256, 0, s_aux>>>(w2, wf2, HID, DIM);
    cudaEventRecord(ev_w2, s_aux);

    gate_kernel<<<NTOK / 8, 256>>>(x, wg, bg, b2, out);
    compact_kernel<<<NEXP, 256>>>();
    permA_kernel<<<dim3(NTOK / BM, NEXP), 256>>>(ei);

    cudaStreamWaitEvent(0, ev_w1, 0);
    ffn1_kernel<<<dim3(NTOK / BM, HID / BN, NEXP), 128>>>(b1);
    cudaStreamWaitEvent(0, ev_w2, 0);
    ffn2_kernel<<<dim3(NTOK / BM, DIM / BN, NEXP * 2), 128>>>(out);
}

// round 15
// speedup vs baseline: 1.0643x; 1.0252x over previous
#include <cuda_runtime.h>
#include <cuda_fp16.h>
#include <cstdint>

#define NTOK 4096
#define DIM  1024
#define NEXP 8
#define HID  4096
#define THR  0.3f

#define BM 128
#define BN 128

// ---------------- scratch (static device memory; no allocs anywhere) ----------------
__device__ float g_c[NTOK * NEXP];
__device__ int   g_idx[NEXP][NTOK];
__device__ float g_wt[NEXP][NTOK];
__device__ int   g_cnt[NEXP];
// fp16 A operands in m16n8k16 fragment layout (one uint4 per lane per 16-row x 16-k block)
__device__ __align__(16) uint32_t g_af[(size_t)NEXP * NTOK * DIM / 2];   // half2 units
__device__ __align__(16) uint32_t g_hf[(size_t)NEXP * NTOK * HID / 2];   // half2 units
// fp16 B operands in fragment layout: uint2 per lane per (kt, n-group-of-8)
__device__ __align__(16) uint2 g_wf1[(size_t)NEXP * (DIM / 16) * (HID / 8) * 32];
__device__ __align__(16) uint2 g_wf2[(size_t)NEXP * (HID / 16) * (DIM / 8) * 32];

// ---------------- helpers ----------------
__device__ __forceinline__ uint32_t pack2(float lo, float hi) {
    uint32_t r;
    asm("cvt.rn.f16x2.f32 %0, %1, %2;" : "=r"(r) : "f"(hi), "f"(lo));
    return r;
}

__device__ __forceinline__ void mma16(float* c, const uint4& a, const uint2& b) {
    asm volatile(
        "mma.sync.aligned.m16n8k16.row.col.f32.f16.f16.f32 "
        "{%0,%1,%2,%3}, {%4,%5,%6,%7}, {%8,%9}, {%0,%1,%2,%3};"
        : "+f"(c[0]), "+f"(c[1]), "+f"(c[2]), "+f"(c[3])
        : "r"(a.x), "r"(a.y), "r"(a.z), "r"(a.w), "r"(b.x), "r"(b.y));
}

__device__ __forceinline__ void red_add_v2(float* p, float v0, float v1) {
    asm volatile("red.global.add.v2.f32 [%0], {%1, %2};"
                 :: "l"(p), "f"(v0), "f"(v1) : "memory");
}

__device__ __forceinline__ float gelu_exact(float v) {
    return 0.5f * v * (1.0f + erff(v * 0.70710678118654752f));
}

// ---------------- kernel 1: gate scores, combine weights, out init with sum(c*b2) ----------------
__global__ __launch_bounds__(256) void gate_kernel(
    const float* __restrict__ x, const float* __restrict__ wg,
    const float* __restrict__ bg, const float* __restrict__ b2,
    float* __restrict__ out)
{
    __shared__ float wgs[DIM * 9];
    int tid = threadIdx.x;
    for (int i = tid; i < DIM * NEXP; i += 256)
        wgs[(i >> 3) * 9 + (i & 7)] = wg[i];
    __syncthreads();

    int lane = tid & 31, wid = tid >> 5;
    int n = blockIdx.x * 8 + wid;

    float s[NEXP];
#pragma unroll
    for (int e = 0; e < NEXP; e++) s[e] = 0.f;

    const float* xr = x + (size_t)n * DIM;
    for (int k = lane; k < DIM; k += 32) {
        float xv = xr[k];
#pragma unroll
        for (int e = 0; e < NEXP; e++) s[e] += xv * wgs[k * 9 + e];
    }
#pragma unroll
    for (int e = 0; e < NEXP; e++)
#pragma unroll
        for (int o = 16; o; o >>= 1)
            s[e] += __shfl_xor_sync(0xffffffffu, s[e], o);

    float mx = -1e30f;
#pragma unroll
    for (int e = 0; e < NEXP; e++) { s[e] += bg[e]; mx = fmaxf(mx, s[e]); }
    float sum = 0.f;
#pragma unroll
    for (int e = 0; e < NEXP; e++) { s[e] = expf(s[e] - mx); sum += s[e]; }
    float inv = 1.f / sum;
#pragma unroll
    for (int e = 0; e < NEXP; e++) s[e] *= inv;

    if (lane == 0) {
        float* gs = out + (size_t)NTOK * DIM + (size_t)n * NEXP;
#pragma unroll
        for (int e = 0; e < NEXP; e++) gs[e] = s[e];
    }

    float msum = 0.f; int cnt = 0;
#pragma unroll
    for (int e = 0; e < NEXP; e++) if (s[e] >= THR) { msum += s[e]; cnt++; }
    int top1 = 0; float best = s[0];
#pragma unroll
    for (int e = 1; e < NEXP; e++) if (s[e] > best) { best = s[e]; top1 = e; }
    float dn = 1.f / (msum + 1e-6f);
    float c[NEXP];
#pragma unroll
    for (int e = 0; e < NEXP; e++)
        c[e] = cnt ? ((s[e] >= THR) ? s[e] * dn : 0.f) : ((e == top1) ? 1.f : 0.f);

    if (lane == 0) {
#pragma unroll
        for (int e = 0; e < NEXP; e++) g_c[n * NEXP + e] = c[e];
    }

    for (int d = lane; d < DIM; d += 32) {
        float a = 0.f;
#pragma unroll
        for (int e = 0; e < NEXP; e++) a += c[e] * b2[e * DIM + d];
        out[(size_t)n * DIM + d] = a;
    }
}

// ---------------- kernel 2: per-expert compaction, 1 CTA per expert, 2 barriers ----------------
__global__ __launch_bounds__(256) void compact_kernel()
{
    const int e = blockIdx.x;
    const int tid = threadIdx.x, lane = tid & 31, wid = tid >> 5;
    __shared__ unsigned masks[8][16];
    __shared__ int wbase[8];

    const int base0 = wid * 512;
    int cnt = 0;
#pragma unroll
    for (int i = 0; i < 16; i++) {
        int n = base0 + i * 32 + lane;
        float c = g_c[n * NEXP + e];
        unsigned m = __ballot_sync(0xffffffffu, c > 0.f);
        if (lane == 0) masks[wid][i] = m;
        cnt += __popc(m);
    }
    __shared__ int wcnt[8];
    if (lane == 0) wcnt[wid] = cnt;
    __syncthreads();
    if (tid == 0) {
        int acc = 0;
#pragma unroll
        for (int w = 0; w < 8; w++) { wbase[w] = acc; acc += wcnt[w]; }
        g_cnt[e] = acc;
    }
    __syncthreads();

    int pos = wbase[wid];
#pragma unroll
    for (int i = 0; i < 16; i++) {
        unsigned m = masks[wid][i];
        if ((m >> lane) & 1u) {
            int n = base0 + i * 32 + lane;
            int p = pos + __popc(m & ((1u << lane) - 1u));
            g_idx[e][p] = n;
            g_wt[e][p]  = g_c[n * NEXP + e];
        }
        pos += __popc(m);
    }
}

// ---------------- kernel 2b: gather + fp16-round expert inputs into fragment layout ----------------
__global__ __launch_bounds__(256) void permA_kernel(const float* __restrict__ ei, int e0)
{
    const int st = blockIdx.x;
    const int e  = e0 + blockIdx.y;
    const int me = g_cnt[e];
    if (st * BM >= me) return;
    const int tid = threadIdx.x;
    uint4* dst = (uint4*)g_af;

#pragma unroll 2
    for (int i = 0; i < 64; i++) {
        int idx  = i * 256 + tid;
        int lane = idx & 31;
        int kq   = (idx >> 5) & 63;
        int rr   = idx >> 11;
        int g = lane >> 2, t = lane & 3;
        int r = rr * 16 + g;
        int s0 = st * BM + r, s1 = s0 + 8;
        int tok0 = (s0 < me) ? g_idx[e][s0] : 0;
        int tok1 = (s1 < me) ? g_idx[e][s1] : 0;
        const float2* r0 = (const float2*)(ei + ((size_t)e * NTOK + tok0) * DIM);
        const float2* r1 = (const float2*)(ei + ((size_t)e * NTOK + tok1) * DIM);
        float2 a00 = r0[kq * 8 + t];
        float2 a01 = r0[kq * 8 + t + 4];
        float2 a10 = r1[kq * 8 + t];
        float2 a11 = r1[kq * 8 + t + 4];
        uint4 v;
        v.x = pack2(a00.x, a00.y);
        v.y = pack2(a10.x, a10.y);
        v.z = pack2(a01.x, a01.y);
        v.w = pack2(a11.x, a11.y);
        dst[(((size_t)(e * 32 + st) * 64 + kq) * 8 + rr) * 32 + lane] = v;
    }
}

// ---------------- kernel 2c: weights -> fp16 B-fragment layout ----------------
__global__ __launch_bounds__(256) void permW_kernel(
    const float* __restrict__ w, uint2* __restrict__ wf, int K, int N)
{
    const int kt = blockIdx.x;
    const int nb = blockIdx.y;
    const int e  = blockIdx.z;
    __shared__ float s[16][132];
    const float* wp = w + (size_t)e * K * N + (size_t)kt * 16 * N + nb * 128;
    const int tid = threadIdx.x;

#pragma unroll
    for (int i = 0; i < 2; i++) {
        int idx = tid + i * 256;
        int row = idx >> 5, c4 = (idx & 31) * 4;
        float4 v = *(const float4*)(wp + (size_t)row * N + c4);
        s[row][c4 + 0] = v.x; s[row][c4 + 1] = v.y;
        s[row][c4 + 2] = v.z; s[row][c4 + 3] = v.w;
    }
    __syncthreads();

    const int NG = N / 8;
    uint2* dst = wf + (((size_t)e * (K / 16) + kt) * NG + nb * 16) * 32;
#pragma unroll
    for (int i = 0; i < 2; i++) {
        int u = tid + i * 256;
        int k2 = u & 3, c8 = (u >> 2) & 7, Gl = u >> 5;
        int n = Gl * 8 + c8;
        uint2 o;
        o.x = pack2(s[2 * k2][n],     s[2 * k2 + 1][n]);
        o.y = pack2(s[2 * k2 + 8][n], s[2 * k2 + 9][n]);
        dst[(size_t)Gl * 32 + c8 * 4 + k2] = o;
    }
}

// =====================================================================================
// FFN GEMMs: 4 warps/CTA (2 wm x 2 wn of 64x64 tiles), CTA 128x128, k-step 16, fp16 MMA.
// NO smem, NO barriers: A and B direct fragment LDGs, register double-buffered.
// Expert-base argument -> two concurrent half-expert pipelines on two streams.
// =====================================================================================

// ---------------- kernel 3: grouped GEMM1: g_hf = frag16(gelu(A @ wf1 + b1)) ----------------
__global__ __launch_bounds__(128, 2) void ffn1_kernel(const float* __restrict__ b1, int e0)
{
    const int e  = e0 + blockIdx.z;
    const int me = g_cnt[e];
    const int mt = blockIdx.x;
    if (mt * BM >= me) return;
    const int n0 = blockIdx.y * BN;

    const int tid  = threadIdx.x;
    const int lane = tid & 31;
    const int wid  = tid >> 5;
    const int wm   = wid >> 1;
    const int wn   = wid & 1;
    const int g    = lane >> 2;
    const int t    = lane & 3;

    const uint4* aF = (const uint4*)g_af;
    const size_t aB = (size_t)(e * 32 + mt) * 64 * 256 + (wm * 4) * 32 + lane;
    const uint2* bW = g_wf1 + (size_t)e * 64 * 512 * 32
                    + ((size_t)(n0 >> 3) + wn * 8) * 32 + lane;

    float acc[4][8][4];
#pragma unroll
    for (int a = 0; a < 4; a++)
#pragma unroll
        for (int b = 0; b < 8; b++)
#pragma unroll
            for (int q = 0; q < 4; q++) acc[a][b][q] = 0.f;

    uint4 a0[4], a1[4];
    uint2 b0[8], b1r[8];

#pragma unroll
    for (int mi = 0; mi < 4; mi++) a0[mi] = aF[aB + mi * 32];
#pragma unroll
    for (int ni = 0; ni < 8; ni++) b0[ni] = bW[ni * 32];

    const int KT = DIM / 16;   // 64
    for (int kt = 0; kt < KT; kt += 2) {
#pragma unroll
        for (int mi = 0; mi < 4; mi++)
            a1[mi] = aF[aB + (size_t)(kt + 1) * 256 + mi * 32];
#pragma unroll
        for (int ni = 0; ni < 8; ni++)
            b1r[ni] = bW[(size_t)(kt + 1) * 16384 + ni * 32];
#pragma unroll
        for (int ni = 0; ni < 8; ni++)
#pragma unroll
            for (int mi = 0; mi < 4; mi++)
                mma16(acc[mi][ni], a0[mi], b0[ni]);
        if (kt + 2 < KT) {
#pragma unroll
            for (int mi = 0; mi < 4; mi++)
                a0[mi] = aF[aB + (size_t)(kt + 2) * 256 + mi * 32];
#pragma unroll
            for (int ni = 0; ni < 8; ni++)
                b0[ni] = bW[(size_t)(kt + 2) * 16384 + ni * 32];
        }
#pragma unroll
        for (int ni = 0; ni < 8; ni++)
#pragma unroll
            for (int mi = 0; mi < 4; mi++)
                mma16(acc[mi][ni], a1[mi], b1r[ni]);
    }

    // epilogue: +b1, exact GELU, pack to fp16 fragment layout for GEMM2
    float bv[8][2];
#pragma unroll
    for (int ni = 0; ni < 8; ni++) {
        int c = n0 + wn * 64 + ni * 8 + 2 * t;
        bv[ni][0] = b1[e * HID + c];
        bv[ni][1] = b1[e * HID + c + 1];
    }
    uint4* hf = (uint4*)g_hf;
#pragma unroll
    for (int mi = 0; mi < 4; mi++) {
#pragma unroll
        for (int p = 0; p < 4; p++) {
            int n0i = 2 * p, n1i = 2 * p + 1;
            uint4 v;
            v.x = pack2(gelu_exact(acc[mi][n0i][0] + bv[n0i][0]),
                        gelu_exact(acc[mi][n0i][1] + bv[n0i][1]));
            v.y = pack2(gelu_exact(acc[mi][n0i][2] + bv[n0i][0]),
                        gelu_exact(acc[mi][n0i][3] + bv[n0i][1]));
            v.z = pack2(gelu_exact(acc[mi][n1i][0] + bv[n1i][0]),
                        gelu_exact(acc[mi][n1i][1] + bv[n1i][1]));
            v.w = pack2(gelu_exact(acc[mi][n1i][2] + bv[n1i][0]),
                        gelu_exact(acc[mi][n1i][3] + bv[n1i][1]));
            int kq = (n0 >> 4) + wn * 4 + p;
            hf[(((size_t)(e * 32 + mt) * 256 + kq) * 8 + (wm * 4 + mi)) * 32 + lane] = v;
        }
    }
}

// ---------------- kernel 4: grouped GEMM2 (K-split x2): out[tok] += c * (g_hf @ wf2) ----------------
__global__ __launch_bounds__(128, 2) void ffn2_kernel(float* __restrict__ out, int e0)
{
    const int e  = e0 + (blockIdx.z >> 1);
    const int sp = blockIdx.z & 1;
    const int me = g_cnt[e];
    const int mt = blockIdx.x;
    if (mt * BM >= me) return;
    const int n0 = blockIdx.y * BN;

    const int tid  = threadIdx.x;
    const int lane = tid & 31;
    const int wid  = tid >> 5;
    const int wm   = wid >> 1;
    const int wn   = wid & 1;
    const int g    = lane >> 2;
    const int t    = lane & 3;

    const uint4* aF = (const uint4*)g_hf;
    const size_t aB = (size_t)(e * 32 + mt) * 256 * 256 + (size_t)(sp * 128) * 256
                    + (wm * 4) * 32 + lane;
    // B fragments: NG = DIM/8 = 128 -> per kt stride = 128*32 = 4096 uint2
    const uint2* bW = g_wf2 + (size_t)e * 256 * 128 * 32 + (size_t)(sp * 128) * 4096
                    + ((size_t)(n0 >> 3) + wn * 8) * 32 + lane;

    float acc[4][8][4];
#pragma unroll
    for (int a = 0; a < 4; a++)
#pragma unroll
        for (int b = 0; b < 8; b++)
#pragma unroll
            for (int q = 0; q < 4; q++) acc[a][b][q] = 0.f;

    uint4 a0[4], a1[4];
    uint2 b0[8], b1r[8];

#pragma unroll
    for (int mi = 0; mi < 4; mi++) a0[mi] = aF[aB + mi * 32];
#pragma unroll
    for (int ni = 0; ni < 8; ni++) b0[ni] = bW[ni * 32];

    const int KT = (HID / 2) / 16;   // 128 per split
    for (int kt = 0; kt < KT; kt += 2) {
#pragma unroll
        for (int mi = 0; mi < 4; mi++)
            a1[mi] = aF[aB + (size_t)(kt + 1) * 256 + mi * 32];
#pragma unroll
        for (int ni = 0; ni < 8; ni++)
            b1r[ni] = bW[(size_t)(kt + 1) * 4096 + ni * 32];
#pragma unroll
        for (int ni = 0; ni < 8; ni++)
#pragma unroll
            for (int mi = 0; mi < 4; mi++)
                mma16(acc[mi][ni], a0[mi], b0[ni]);
        if (kt + 2 < KT) {
#pragma unroll
            for (int mi = 0; mi < 4; mi++)
                a0[mi] = aF[aB + (size_t)(kt + 2) * 256 + mi * 32];
#pragma unroll
            for (int ni = 0; ni < 8; ni++)
                b0[ni] = bW[(size_t)(kt + 2) * 4096 + ni * 32];
        }
#pragma unroll
        for (int ni = 0; ni < 8; ni++)
#pragma unroll
            for (int mi = 0; mi < 4; mi++)
                mma16(acc[mi][ni], a1[mi], b1r[ni]);
    }

    // epilogue: scaled vector scatter-add (red.global.add.v2.f32); split partials add
#pragma unroll
    for (int mi = 0; mi < 4; mi++) {
#pragma unroll
        for (int h2 = 0; h2 < 2; h2++) {
            int row = wm * 64 + mi * 16 + g + 8 * h2;
            int ss = mt * BM + row;
            if (ss < me) {
                int tok  = g_idx[e][ss];
                float wc = g_wt[e][ss];
                float* orow = out + (size_t)tok * DIM;
#pragma unroll
                for (int ni = 0; ni < 8; ni++) {
                    int col = n0 + wn * 64 + ni * 8 + 2 * t;
                    red_add_v2(orow + col,
                               wc * acc[mi][ni][2 * h2 + 0],
                               wc * acc[mi][ni][2 * h2 + 1]);
                }
            }
        }
    }
}

// ---------------- launch ----------------
extern "C" void kernel_launch(void* const* d_in, const int* in_sizes, int n_in,
                              void* d_out, int out_size)
{
    (void)in_sizes; (void)n_in; (void)out_size;
    const float* x  = (const float*)d_in[0];
    const float* ei = (const float*)d_in[1];
    const float* wg = (const float*)d_in[2];
    const float* bg = (const float*)d_in[3];
    const float* w1 = (const float*)d_in[4];
    const float* b1 = (const float*)d_in[5];
    const float* w2 = (const float*)d_in[6];
    const float* b2 = (const float*)d_in[7];
    float* out = (float*)d_out;

    uint2* wf1; cudaGetSymbolAddress((void**)&wf1, g_wf1);
    uint2* wf2; cudaGetSymbolAddress((void**)&wf2, g_wf2);

    // lazily-created single side stream + events (same resource budget that passed
    // the allocation guard in prior rounds; captured work identical every call)
    static cudaStream_t s_aux = nullptr;
    static cudaEvent_t ev_fork = nullptr, ev_w1 = nullptr, ev_w2 = nullptr;
    static cudaEvent_t ev_compact = nullptr, ev_done = nullptr;
    if (!s_aux) {
        cudaStreamCreateWithFlags(&s_aux, cudaStreamNonBlocking);
        cudaEventCreateWithFlags(&ev_fork, cudaEventDisableTiming);
        cudaEventCreateWithFlags(&ev_w1, cudaEventDisableTiming);
        cudaEventCreateWithFlags(&ev_w2, cudaEventDisableTiming);
        cudaEventCreateWithFlags(&ev_compact, cudaEventDisableTiming);
        cudaEventCreateWithFlags(&ev_done, cudaEventDisableTiming);
    }

    // fork: weight permutation first on the side stream
    cudaEventRecord(ev_fork, 0);
    cudaStreamWaitEvent(s_aux, ev_fork, 0);
    permW_kernel<<<dim3(DIM / 16, HID / 128, NEXP), 256, 0, s_aux>>>(w1, wf1, DIM, HID);
    cudaEventRecord(ev_w1, s_aux);
    permW_kernel<<<dim3(HID / 16, DIM / 128, NEXP), 256, 0, s_aux>>>(w2, wf2, HID, DIM);
    cudaEventRecord(ev_w2, s_aux);

    // gate chain on origin stream
    gate_kernel<<<NTOK / 8, 256>>>(x, wg, bg, b2, out);
    compact_kernel<<<NEXP, 256>>>();
    cudaEventRecord(ev_compact, 0);

    // pipeline A (experts 0..3) on origin stream
    permA_kernel<<<dim3(NTOK / BM, 4), 256>>>(ei, 0);
    cudaStreamWaitEvent(0, ev_w1, 0);
    ffn1_kernel<<<dim3(NTOK / BM, HID / BN, 4), 128>>>(b1, 0);
    cudaStreamWaitEvent(0, ev_w2, 0);
    ffn2_kernel<<<dim3(NTOK / BM, DIM / BN, 8), 128>>>(out, 0);

    // pipeline B (experts 4..7) on side stream (already ordered after permW1/permW2)
    cudaStreamWaitEvent(s_aux, ev_compact, 0);
    permA_kernel<<<dim3(NTOK / BM, 4), 256, 0, s_aux>>>(ei, 4);
    ffn1_kernel<<<dim3(NTOK / BM, HID / BN, 4), 128, 0, s_aux>>>(b1, 4);
    ffn2_kernel<<<dim3(NTOK / BM, DIM / BN, 8), 128, 0, s_aux>>>(out, 4);
    cudaEventRecord(ev_done, s_aux);

    // join
    cudaStreamWaitEvent(0, ev_done, 0);
}

// round 16
// speedup vs baseline: 1.0830x; 1.0175x over previous
#include <cuda_runtime.h>
#include <cuda_fp16.h>
#include <cstdint>

#define NTOK 4096
#define DIM  1024
#define NEXP 8
#define HID  4096
#define THR  0.3f

#define BM 128
#define BN 128

// ---------------- scratch (static device memory; no allocs anywhere) ----------------
__device__ float g_c[NTOK * NEXP];
__device__ int   g_idx[NEXP][NTOK];
__device__ float g_wt[NEXP][NTOK];
__device__ int   g_cnt[NEXP];
// fp16 A operands in m16n8k16 fragment layout (one uint4 per lane per 16-row x 16-k block)
__device__ __align__(16) uint32_t g_af[(size_t)NEXP * NTOK * DIM / 2];   // half2 units
__device__ __align__(16) uint32_t g_hf[(size_t)NEXP * NTOK * HID / 2];   // half2 units
// fp16 B operands in fragment layout: uint2 per lane per (kt, n-group-of-8)
__device__ __align__(16) uint2 g_wf1[(size_t)NEXP * (DIM / 16) * (HID / 8) * 32];
__device__ __align__(16) uint2 g_wf2[(size_t)NEXP * (HID / 16) * (DIM / 8) * 32];

// ---------------- helpers ----------------
__device__ __forceinline__ uint32_t pack2(float lo, float hi) {
    uint32_t r;
    asm("cvt.rn.f16x2.f32 %0, %1, %2;" : "=r"(r) : "f"(hi), "f"(lo));
    return r;
}

__device__ __forceinline__ void mma16(float* c, const uint4& a, const uint2& b) {
    asm volatile(
        "mma.sync.aligned.m16n8k16.row.col.f32.f16.f16.f32 "
        "{%0,%1,%2,%3}, {%4,%5,%6,%7}, {%8,%9}, {%0,%1,%2,%3};"
        : "+f"(c[0]), "+f"(c[1]), "+f"(c[2]), "+f"(c[3])
        : "r"(a.x), "r"(a.y), "r"(a.z), "r"(a.w), "r"(b.x), "r"(b.y));
}

__device__ __forceinline__ void red_add_v2(float* p, float v0, float v1) {
    asm volatile("red.global.add.v2.f32 [%0], {%1, %2};"
                 :: "l"(p), "f"(v0), "f"(v1) : "memory");
}

__device__ __forceinline__ float gelu_exact(float v) {
    return 0.5f * v * (1.0f + erff(v * 0.70710678118654752f));
}

// ---------------- kernel 1: gate scores, combine weights, out init with sum(c*b2) ----------------
__global__ __launch_bounds__(256) void gate_kernel(
    const float* __restrict__ x, const float* __restrict__ wg,
    const float* __restrict__ bg, const float* __restrict__ b2,
    float* __restrict__ out)
{
    __shared__ float wgs[DIM * 9];
    int tid = threadIdx.x;
    for (int i = tid; i < DIM * NEXP; i += 256)
        wgs[(i >> 3) * 9 + (i & 7)] = wg[i];
    __syncthreads();

    int lane = tid & 31, wid = tid >> 5;
    int n = blockIdx.x * 8 + wid;

    float s[NEXP];
#pragma unroll
    for (int e = 0; e < NEXP; e++) s[e] = 0.f;

    const float* xr = x + (size_t)n * DIM;
    for (int k = lane; k < DIM; k += 32) {
        float xv = xr[k];
#pragma unroll
        for (int e = 0; e < NEXP; e++) s[e] += xv * wgs[k * 9 + e];
    }
#pragma unroll
    for (int e = 0; e < NEXP; e++)
#pragma unroll
        for (int o = 16; o; o >>= 1)
            s[e] += __shfl_xor_sync(0xffffffffu, s[e], o);

    float mx = -1e30f;
#pragma unroll
    for (int e = 0; e < NEXP; e++) { s[e] += bg[e]; mx = fmaxf(mx, s[e]); }
    float sum = 0.f;
#pragma unroll
    for (int e = 0; e < NEXP; e++) { s[e] = expf(s[e] - mx); sum += s[e]; }
    float inv = 1.f / sum;
#pragma unroll
    for (int e = 0; e < NEXP; e++) s[e] *= inv;

    if (lane == 0) {
        float* gs = out + (size_t)NTOK * DIM + (size_t)n * NEXP;
#pragma unroll
        for (int e = 0; e < NEXP; e++) gs[e] = s[e];
    }

    float msum = 0.f; int cnt = 0;
#pragma unroll
    for (int e = 0; e < NEXP; e++) if (s[e] >= THR) { msum += s[e]; cnt++; }
    int top1 = 0; float best = s[0];
#pragma unroll
    for (int e = 1; e < NEXP; e++) if (s[e] > best) { best = s[e]; top1 = e; }
    float dn = 1.f / (msum + 1e-6f);
    float c[NEXP];
#pragma unroll
    for (int e = 0; e < NEXP; e++)
        c[e] = cnt ? ((s[e] >= THR) ? s[e] * dn : 0.f) : ((e == top1) ? 1.f : 0.f);

    if (lane == 0) {
#pragma unroll
        for (int e = 0; e < NEXP; e++) g_c[n * NEXP + e] = c[e];
    }

    for (int d = lane; d < DIM; d += 32) {
        float a = 0.f;
#pragma unroll
        for (int e = 0; e < NEXP; e++) a += c[e] * b2[e * DIM + d];
        out[(size_t)n * DIM + d] = a;
    }
}

// ---------------- kernel 2: per-expert compaction, 1 CTA per expert, 2 barriers ----------------
__global__ __launch_bounds__(256) void compact_kernel()
{
    const int e = blockIdx.x;
    const int tid = threadIdx.x, lane = tid & 31, wid = tid >> 5;
    __shared__ unsigned masks[8][16];
    __shared__ int wbase[8];

    const int base0 = wid * 512;
    int cnt = 0;
#pragma unroll
    for (int i = 0; i < 16; i++) {
        int n = base0 + i * 32 + lane;
        float c = g_c[n * NEXP + e];
        unsigned m = __ballot_sync(0xffffffffu, c > 0.f);
        if (lane == 0) masks[wid][i] = m;
        cnt += __popc(m);
    }
    __shared__ int wcnt[8];
    if (lane == 0) wcnt[wid] = cnt;
    __syncthreads();
    if (tid == 0) {
        int acc = 0;
#pragma unroll
        for (int w = 0; w < 8; w++) { wbase[w] = acc; acc += wcnt[w]; }
        g_cnt[e] = acc;
    }
    __syncthreads();

    int pos = wbase[wid];
#pragma unroll
    for (int i = 0; i < 16; i++) {
        unsigned m = masks[wid][i];
        if ((m >> lane) & 1u) {
            int n = base0 + i * 32 + lane;
            int p = pos + __popc(m & ((1u << lane) - 1u));
            g_idx[e][p] = n;
            g_wt[e][p]  = g_c[n * NEXP + e];
        }
        pos += __popc(m);
    }
}

// ---------------- kernel 2b: gather + fp16-round expert inputs into fragment layout ----------------
__global__ __launch_bounds__(256) void permA_kernel(const float* __restrict__ ei, int e0)
{
    const int st = blockIdx.x;
    const int e  = e0 + blockIdx.y;
    const int me = g_cnt[e];
    if (st * BM >= me) return;
    const int tid = threadIdx.x;
    uint4* dst = (uint4*)g_af;

#pragma unroll 2
    for (int i = 0; i < 64; i++) {
        int idx  = i * 256 + tid;
        int lane = idx & 31;
        int kq   = (idx >> 5) & 63;
        int rr   = idx >> 11;
        int g = lane >> 2, t = lane & 3;
        int r = rr * 16 + g;
        int s0 = st * BM + r, s1 = s0 + 8;
        int tok0 = (s0 < me) ? g_idx[e][s0] : 0;
        int tok1 = (s1 < me) ? g_idx[e][s1] : 0;
        const float2* r0 = (const float2*)(ei + ((size_t)e * NTOK + tok0) * DIM);
        const float2* r1 = (const float2*)(ei + ((size_t)e * NTOK + tok1) * DIM);
        float2 a00 = r0[kq * 8 + t];
        float2 a01 = r0[kq * 8 + t + 4];
        float2 a10 = r1[kq * 8 + t];
        float2 a11 = r1[kq * 8 + t + 4];
        uint4 v;
        v.x = pack2(a00.x, a00.y);
        v.y = pack2(a10.x, a10.y);
        v.z = pack2(a01.x, a01.y);
        v.w = pack2(a11.x, a11.y);
        dst[(((size_t)(e * 32 + st) * 64 + kq) * 8 + rr) * 32 + lane] = v;
    }
}

// ---------------- kernel 2c: weights -> fp16 B-fragment layout ----------------
__global__ __launch_bounds__(256) void permW_kernel(
    const float* __restrict__ w, uint2* __restrict__ wf, int K, int N)
{
    const int kt = blockIdx.x;
    const int nb = blockIdx.y;
    const int e  = blockIdx.z;
    __shared__ float s[16][132];
    const float* wp = w + (size_t)e * K * N + (size_t)kt * 16 * N + nb * 128;
    const int tid = threadIdx.x;

#pragma unroll
    for (int i = 0; i < 2; i++) {
        int idx = tid + i * 256;
        int row = idx >> 5, c4 = (idx & 31) * 4;
        float4 v = *(const float4*)(wp + (size_t)row * N + c4);
        s[row][c4 + 0] = v.x; s[row][c4 + 1] = v.y;
        s[row][c4 + 2] = v.z; s[row][c4 + 3] = v.w;
    }
    __syncthreads();

    const int NG = N / 8;
    uint2* dst = wf + (((size_t)e * (K / 16) + kt) * NG + nb * 16) * 32;
#pragma unroll
    for (int i = 0; i < 2; i++) {
        int u = tid + i * 256;
        int k2 = u & 3, c8 = (u >> 2) & 7, Gl = u >> 5;
        int n = Gl * 8 + c8;
        uint2 o;
        o.x = pack2(s[2 * k2][n],     s[2 * k2 + 1][n]);
        o.y = pack2(s[2 * k2 + 8][n], s[2 * k2 + 9][n]);
        dst[(size_t)Gl * 32 + c8 * 4 + k2] = o;
    }
}

// =====================================================================================
// FFN GEMMs: 4 warps/CTA (2 wm x 2 wn of 64x64 tiles), CTA 128x128, k-step 16, fp16 MMA.
// NO smem, NO barriers. 3-stage register pipeline (prefetch distance 2 kt >= L2 latency),
// fully unrolled so mod-3 buffer indices resolve to registers.
// =====================================================================================

// ---------------- kernel 3: grouped GEMM1: g_hf = frag16(gelu(A @ wf1 + b1)) ----------------
__global__ __launch_bounds__(128, 2) void ffn1_kernel(const float* __restrict__ b1, int e0)
{
    const int e  = e0 + blockIdx.z;
    const int me = g_cnt[e];
    const int mt = blockIdx.x;
    if (mt * BM >= me) return;
    const int n0 = blockIdx.y * BN;

    const int tid  = threadIdx.x;
    const int lane = tid & 31;
    const int wid  = tid >> 5;
    const int wm   = wid >> 1;
    const int wn   = wid & 1;
    const int g    = lane >> 2;
    const int t    = lane & 3;

    const uint4* aF = (const uint4*)g_af;
    const size_t aB = (size_t)(e * 32 + mt) * 64 * 256 + (wm * 4) * 32 + lane;
    const uint2* bW = g_wf1 + (size_t)e * 64 * 512 * 32
                    + ((size_t)(n0 >> 3) + wn * 8) * 32 + lane;

    float acc[4][8][4];
#pragma unroll
    for (int a = 0; a < 4; a++)
#pragma unroll
        for (int b = 0; b < 8; b++)
#pragma unroll
            for (int q = 0; q < 4; q++) acc[a][b][q] = 0.f;

    uint4 ab[3][4];
    uint2 bb[3][8];

    // prime stages 0,1
#pragma unroll
    for (int s = 0; s < 2; s++) {
#pragma unroll
        for (int mi = 0; mi < 4; mi++)
            ab[s][mi] = aF[aB + (size_t)s * 256 + mi * 32];
#pragma unroll
        for (int ni = 0; ni < 8; ni++)
            bb[s][ni] = bW[(size_t)s * 16384 + ni * 32];
    }

    const int KT = DIM / 16;   // 64
#pragma unroll
    for (int kt = 0; kt < KT; kt++) {
        const int cur = kt % 3;
        if (kt + 2 < KT) {
            const int nx = (kt + 2) % 3;
#pragma unroll
            for (int mi = 0; mi < 4; mi++)
                ab[nx][mi] = aF[aB + (size_t)(kt + 2) * 256 + mi * 32];
#pragma unroll
            for (int ni = 0; ni < 8; ni++)
                bb[nx][ni] = bW[(size_t)(kt + 2) * 16384 + ni * 32];
        }
#pragma unroll
        for (int ni = 0; ni < 8; ni++)
#pragma unroll
            for (int mi = 0; mi < 4; mi++)
                mma16(acc[mi][ni], ab[cur][mi], bb[cur][ni]);
    }

    // epilogue: +b1, exact GELU, pack to fp16 fragment layout for GEMM2
    float bv[8][2];
#pragma unroll
    for (int ni = 0; ni < 8; ni++) {
        int c = n0 + wn * 64 + ni * 8 + 2 * t;
        bv[ni][0] = b1[e * HID + c];
        bv[ni][1] = b1[e * HID + c + 1];
    }
    uint4* hf = (uint4*)g_hf;
#pragma unroll
    for (int mi = 0; mi < 4; mi++) {
#pragma unroll
        for (int p = 0; p < 4; p++) {
            int n0i = 2 * p, n1i = 2 * p + 1;
            uint4 v;
            v.x = pack2(gelu_exact(acc[mi][n0i][0] + bv[n0i][0]),
                        gelu_exact(acc[mi][n0i][1] + bv[n0i][1]));
            v.y = pack2(gelu_exact(acc[mi][n0i][2] + bv[n0i][0]),
                        gelu_exact(acc[mi][n0i][3] + bv[n0i][1]));
            v.z = pack2(gelu_exact(acc[mi][n1i][0] + bv[n1i][0]),
                        gelu_exact(acc[mi][n1i][1] + bv[n1i][1]));
            v.w = pack2(gelu_exact(acc[mi][n1i][2] + bv[n1i][0]),
                        gelu_exact(acc[mi][n1i][3] + bv[n1i][1]));
            int kq = (n0 >> 4) + wn * 4 + p;
            hf[(((size_t)(e * 32 + mt) * 256 + kq) * 8 + (wm * 4 + mi)) * 32 + lane] = v;
        }
    }
}

// ---------------- kernel 4: grouped GEMM2 (K-split x2): out[tok] += c * (g_hf @ wf2) ----------------
__global__ __launch_bounds__(128, 2) void ffn2_kernel(float* __restrict__ out, int e0)
{
    const int e  = e0 + (blockIdx.z >> 1);
    const int sp = blockIdx.z & 1;
    const int me = g_cnt[e];
    const int mt = blockIdx.x;
    if (mt * BM >= me) return;
    const int n0 = blockIdx.y * BN;

    const int tid  = threadIdx.x;
    const int lane = tid & 31;
    const int wid  = tid >> 5;
    const int wm   = wid >> 1;
    const int wn   = wid & 1;
    const int g    = lane >> 2;
    const int t    = lane & 3;

    const uint4* aF = (const uint4*)g_hf;
    const size_t aB = (size_t)(e * 32 + mt) * 256 * 256 + (size_t)(sp * 128) * 256
                    + (wm * 4) * 32 + lane;
    // B fragments: NG = DIM/8 = 128 -> per kt stride = 128*32 = 4096 uint2
    const uint2* bW = g_wf2 + (size_t)e * 256 * 128 * 32 + (size_t)(sp * 128) * 4096
                    + ((size_t)(n0 >> 3) + wn * 8) * 32 + lane;

    float acc[4][8][4];
#pragma unroll
    for (int a = 0; a < 4; a++)
#pragma unroll
        for (int b = 0; b < 8; b++)
#pragma unroll
            for (int q = 0; q < 4; q++) acc[a][b][q] = 0.f;

    uint4 ab[3][4];
    uint2 bb[3][8];

#pragma unroll
    for (int s = 0; s < 2; s++) {
#pragma unroll
        for (int mi = 0; mi < 4; mi++)
            ab[s][mi] = aF[aB + (size_t)s * 256 + mi * 32];
#pragma unroll
        for (int ni = 0; ni < 8; ni++)
            bb[s][ni] = bW[(size_t)s * 4096 + ni * 32];
    }

    const int KT = (HID / 2) / 16;   // 128 per split
#pragma unroll
    for (int kt = 0; kt < KT; kt++) {
        const int cur = kt % 3;
        if (kt + 2 < KT) {
            const int nx = (kt + 2) % 3;
#pragma unroll
            for (int mi = 0; mi < 4; mi++)
                ab[nx][mi] = aF[aB + (size_t)(kt + 2) * 256 + mi * 32];
#pragma unroll
            for (int ni = 0; ni < 8; ni++)
                bb[nx][ni] = bW[(size_t)(kt + 2) * 4096 + ni * 32];
        }
#pragma unroll
        for (int ni = 0; ni < 8; ni++)
#pragma unroll
            for (int mi = 0; mi < 4; mi++)
                mma16(acc[mi][ni], ab[cur][mi], bb[cur][ni]);
    }

    // epilogue: scaled vector scatter-add (red.global.add.v2.f32); split partials add
#pragma unroll
    for (int mi = 0; mi < 4; mi++) {
#pragma unroll
        for (int h2 = 0; h2 < 2; h2++) {
            int row = wm * 64 + mi * 16 + g + 8 * h2;
            int ss = mt * BM + row;
            if (ss < me) {
                int tok  = g_idx[e][ss];
                float wc = g_wt[e][ss];
                float* orow = out + (size_t)tok * DIM;
#pragma unroll
                for (int ni = 0; ni < 8; ni++) {
                    int col = n0 + wn * 64 + ni * 8 + 2 * t;
                    red_add_v2(orow + col,
                               wc * acc[mi][ni][2 * h2 + 0],
                               wc * acc[mi][ni][2 * h2 + 1]);
                }
            }
        }
    }
}

// ---------------- launch ----------------
extern "C" void kernel_launch(void* const* d_in, const int* in_sizes, int n_in,
                              void* d_out, int out_size)
{
    (void)in_sizes; (void)n_in; (void)out_size;
    const float* x  = (const float*)d_in[0];
    const float* ei = (const float*)d_in[1];
    const float* wg = (const float*)d_in[2];
    const float* bg = (const float*)d_in[3];
    const float* w1 = (const float*)d_in[4];
    const float* b1 = (const float*)d_in[5];
    const float* w2 = (const float*)d_in[6];
    const float* b2 = (const float*)d_in[7];
    float* out = (float*)d_out;

    uint2* wf1; cudaGetSymbolAddress((void**)&wf1, g_wf1);
    uint2* wf2; cudaGetSymbolAddress((void**)&wf2, g_wf2);

    // lazily-created single side stream + events (same resource budget that passed
    // the allocation guard in prior rounds; captured work identical every call)
    static cudaStream_t s_aux = nullptr;
    static cudaEvent_t ev_fork = nullptr, ev_w1 = nullptr, ev_w2 = nullptr;
    static cudaEvent_t ev_compact = nullptr, ev_done = nullptr;
    if (!s_aux) {
        cudaStreamCreateWithFlags(&s_aux, cudaStreamNonBlocking);
        cudaEventCreateWithFlags(&ev_fork, cudaEventDisableTiming);
        cudaEventCreateWithFlags(&ev_w1, cudaEventDisableTiming);
        cudaEventCreateWithFlags(&ev_w2, cudaEventDisableTiming);
        cudaEventCreateWithFlags(&ev_compact, cudaEventDisableTiming);
        cudaEventCreateWithFlags(&ev_done, cudaEventDisableTiming);
    }

    // fork: weight permutation first on the side stream
    cudaEventRecord(ev_fork, 0);
    cudaStreamWaitEvent(s_aux, ev_fork, 0);
    permW_kernel<<<dim3(DIM / 16, HID / 128, NEXP), 256, 0, s_aux>>>(w1, wf1, DIM, HID);
    cudaEventRecord(ev_w1, s_aux);
    permW_kernel<<<dim3(HID / 16, DIM / 128, NEXP), 256, 0, s_aux>>>(w2, wf2, HID, DIM);
    cudaEventRecord(ev_w2, s_aux);

    // gate chain on origin stream
    gate_kernel<<<NTOK / 8, 256>>>(x, wg, bg, b2, out);
    compact_kernel<<<NEXP, 256>>>();
    cudaEventRecord(ev_compact, 0);

    // pipeline A (experts 0..3) on origin stream
    permA_kernel<<<dim3(NTOK / BM, 4), 256>>>(ei, 0);
    cudaStreamWaitEvent(0, ev_w1, 0);
    ffn1_kernel<<<dim3(NTOK / BM, HID / BN, 4), 128>>>(b1, 0);
    cudaStreamWaitEvent(0, ev_w2, 0);
    ffn2_kernel<<<dim3(NTOK / BM, DIM / BN, 8), 128>>>(out, 0);

    // pipeline B (experts 4..7) on side stream (already ordered after permW1/permW2)
    cudaStreamWaitEvent(s_aux, ev_compact, 0);
    permA_kernel<<<dim3(NTOK / BM, 4), 256, 0, s_aux>>>(ei, 4);
    ffn1_kernel<<<dim3(NTOK / BM, HID / BN, 4), 128, 0, s_aux>>>(b1, 4);
    ffn2_kernel<<<dim3(NTOK / BM, DIM / BN, 8), 128, 0, s_aux>>>(out, 4);
    cudaEventRecord(ev_done, s_aux);

    // join
    cudaStreamWaitEvent(0, ev_done, 0);
}

// round 17
// speedup vs baseline: 1.1110x; 1.0258x over previous
#include <cuda_runtime.h>
#include <cuda_fp16.h>
#include <cstdint>

#define NTOK 4096
#define DIM  1024
#define NEXP 8
#define HID  4096
#define THR  0.3f

#define BM 128
#define BN 128

// ---------------- scratch (static device memory; no allocs anywhere) ----------------
__device__ float g_c[NTOK * NEXP];
__device__ int   g_idx[NEXP][NTOK];
__device__ float g_wt[NEXP][NTOK];
__device__ int   g_cnt[NEXP];
// fp16 A operands in m16n8k16 fragment layout (one uint4 per lane per 16-row x 16-k block)
__device__ __align__(16) uint32_t g_af[(size_t)NEXP * NTOK * DIM / 2];   // half2 units
__device__ __align__(16) uint32_t g_hf[(size_t)NEXP * NTOK * HID / 2];   // half2 units
// fp16 B operands, PAIRED fragment layout: uint4 per lane per (kt, n-group-PAIR of 16)
//   uint4 = { frag(2P).b0, frag(2P).b1, frag(2P+1).b0, frag(2P+1).b1 }
__device__ __align__(16) uint4 g_wf1[(size_t)NEXP * (DIM / 16) * (HID / 16) * 32];
__device__ __align__(16) uint4 g_wf2[(size_t)NEXP * (HID / 16) * (DIM / 16) * 32];

// ---------------- helpers ----------------
__device__ __forceinline__ uint32_t pack2(float lo, float hi) {
    uint32_t r;
    asm("cvt.rn.f16x2.f32 %0, %1, %2;" : "=r"(r) : "f"(hi), "f"(lo));
    return r;
}

__device__ __forceinline__ void mma16(float* c, const uint4& a, uint32_t b0, uint32_t b1) {
    asm volatile(
        "mma.sync.aligned.m16n8k16.row.col.f32.f16.f16.f32 "
        "{%0,%1,%2,%3}, {%4,%5,%6,%7}, {%8,%9}, {%0,%1,%2,%3};"
        : "+f"(c[0]), "+f"(c[1]), "+f"(c[2]), "+f"(c[3])
        : "r"(a.x), "r"(a.y), "r"(a.z), "r"(a.w), "r"(b0), "r"(b1));
}

__device__ __forceinline__ void red_add_v2(float* p, float v0, float v1) {
    asm volatile("red.global.add.v2.f32 [%0], {%1, %2};"
                 :: "l"(p), "f"(v0), "f"(v1) : "memory");
}

__device__ __forceinline__ float gelu_exact(float v) {
    return 0.5f * v * (1.0f + erff(v * 0.70710678118654752f));
}

// ---------------- kernel 1: gate scores, combine weights, out init with sum(c*b2) ----------------
__global__ __launch_bounds__(256) void gate_kernel(
    const float* __restrict__ x, const float* __restrict__ wg,
    const float* __restrict__ bg, const float* __restrict__ b2,
    float* __restrict__ out)
{
    __shared__ float wgs[DIM * 9];
    int tid = threadIdx.x;
    for (int i = tid; i < DIM * NEXP; i += 256)
        wgs[(i >> 3) * 9 + (i & 7)] = wg[i];
    __syncthreads();

    int lane = tid & 31, wid = tid >> 5;
    int n = blockIdx.x * 8 + wid;

    float s[NEXP];
#pragma unroll
    for (int e = 0; e < NEXP; e++) s[e] = 0.f;

    const float* xr = x + (size_t)n * DIM;
    for (int k = lane; k < DIM; k += 32) {
        float xv = xr[k];
#pragma unroll
        for (int e = 0; e < NEXP; e++) s[e] += xv * wgs[k * 9 + e];
    }
#pragma unroll
    for (int e = 0; e < NEXP; e++)
#pragma unroll
        for (int o = 16; o; o >>= 1)
            s[e] += __shfl_xor_sync(0xffffffffu, s[e], o);

    float mx = -1e30f;
#pragma unroll
    for (int e = 0; e < NEXP; e++) { s[e] += bg[e]; mx = fmaxf(mx, s[e]); }
    float sum = 0.f;
#pragma unroll
    for (int e = 0; e < NEXP; e++) { s[e] = expf(s[e] - mx); sum += s[e]; }
    float inv = 1.f / sum;
#pragma unroll
    for (int e = 0; e < NEXP; e++) s[e] *= inv;

    if (lane == 0) {
        float* gs = out + (size_t)NTOK * DIM + (size_t)n * NEXP;
#pragma unroll
        for (int e = 0; e < NEXP; e++) gs[e] = s[e];
    }

    float msum = 0.f; int cnt = 0;
#pragma unroll
    for (int e = 0; e < NEXP; e++) if (s[e] >= THR) { msum += s[e]; cnt++; }
    int top1 = 0; float best = s[0];
#pragma unroll
    for (int e = 1; e < NEXP; e++) if (s[e] > best) { best = s[e]; top1 = e; }
    float dn = 1.f / (msum + 1e-6f);
    float c[NEXP];
#pragma unroll
    for (int e = 0; e < NEXP; e++)
        c[e] = cnt ? ((s[e] >= THR) ? s[e] * dn : 0.f) : ((e == top1) ? 1.f : 0.f);

    if (lane == 0) {
#pragma unroll
        for (int e = 0; e < NEXP; e++) g_c[n * NEXP + e] = c[e];
    }

    for (int d = lane; d < DIM; d += 32) {
        float a = 0.f;
#pragma unroll
        for (int e = 0; e < NEXP; e++) a += c[e] * b2[e * DIM + d];
        out[(size_t)n * DIM + d] = a;
    }
}

// ---------------- kernel 2: per-expert compaction, 1 CTA per expert, 2 barriers ----------------
__global__ __launch_bounds__(256) void compact_kernel()
{
    const int e = blockIdx.x;
    const int tid = threadIdx.x, lane = tid & 31, wid = tid >> 5;
    __shared__ unsigned masks[8][16];
    __shared__ int wbase[8];

    const int base0 = wid * 512;
    int cnt = 0;
#pragma unroll
    for (int i = 0; i < 16; i++) {
        int n = base0 + i * 32 + lane;
        float c = g_c[n * NEXP + e];
        unsigned m = __ballot_sync(0xffffffffu, c > 0.f);
        if (lane == 0) masks[wid][i] = m;
        cnt += __popc(m);
    }
    __shared__ int wcnt[8];
    if (lane == 0) wcnt[wid] = cnt;
    __syncthreads();
    if (tid == 0) {
        int acc = 0;
#pragma unroll
        for (int w = 0; w < 8; w++) { wbase[w] = acc; acc += wcnt[w]; }
        g_cnt[e] = acc;
    }
    __syncthreads();

    int pos = wbase[wid];
#pragma unroll
    for (int i = 0; i < 16; i++) {
        unsigned m = masks[wid][i];
        if ((m >> lane) & 1u) {
            int n = base0 + i * 32 + lane;
            int p = pos + __popc(m & ((1u << lane) - 1u));
            g_idx[e][p] = n;
            g_wt[e][p]  = g_c[n * NEXP + e];
        }
        pos += __popc(m);
    }
}

// ---------------- kernel 2b: gather + fp16-round expert inputs into fragment layout ----------------
__global__ __launch_bounds__(256) void permA_kernel(const float* __restrict__ ei, int e0)
{
    const int st = blockIdx.x;
    const int e  = e0 + blockIdx.y;
    const int me = g_cnt[e];
    if (st * BM >= me) return;
    const int tid = threadIdx.x;
    uint4* dst = (uint4*)g_af;

#pragma unroll 2
    for (int i = 0; i < 64; i++) {
        int idx  = i * 256 + tid;
        int lane = idx & 31;
        int kq   = (idx >> 5) & 63;
        int rr   = idx >> 11;
        int g = lane >> 2, t = lane & 3;
        int r = rr * 16 + g;
        int s0 = st * BM + r, s1 = s0 + 8;
        int tok0 = (s0 < me) ? g_idx[e][s0] : 0;
        int tok1 = (s1 < me) ? g_idx[e][s1] : 0;
        const float2* r0 = (const float2*)(ei + ((size_t)e * NTOK + tok0) * DIM);
        const float2* r1 = (const float2*)(ei + ((size_t)e * NTOK + tok1) * DIM);
        float2 a00 = r0[kq * 8 + t];
        float2 a01 = r0[kq * 8 + t + 4];
        float2 a10 = r1[kq * 8 + t];
        float2 a11 = r1[kq * 8 + t + 4];
        uint4 v;
        v.x = pack2(a00.x, a00.y);
        v.y = pack2(a10.x, a10.y);
        v.z = pack2(a01.x, a01.y);
        v.w = pack2(a11.x, a11.y);
        dst[(((size_t)(e * 32 + st) * 64 + kq) * 8 + rr) * 32 + lane] = v;
    }
}

// ---------------- kernel 2c: weights -> PAIRED fp16 B-fragment layout ----------------
// Per (kt, P): 32 lanes x uint4 { frag(G=2P)[lane].b0, .b1, frag(G=2P+1)[lane].b0, .b1 }.
// Thread u (0..255): k2=u&3, c8=(u>>2)&7, P=u>>5 (local 0..7); lane=c8*4+k2=u&31.
__global__ __launch_bounds__(256) void permW_kernel(
    const float* __restrict__ w, uint4* __restrict__ wf, int K, int N)
{
    const int kt = blockIdx.x;
    const int nb = blockIdx.y;
    const int e  = blockIdx.z;
    __shared__ float s[16][132];
    const float* wp = w + (size_t)e * K * N + (size_t)kt * 16 * N + nb * 128;
    const int tid = threadIdx.x;

#pragma unroll
    for (int i = 0; i < 2; i++) {
        int idx = tid + i * 256;
        int row = idx >> 5, c4 = (idx & 31) * 4;
        float4 v = *(const float4*)(wp + (size_t)row * N + c4);
        s[row][c4 + 0] = v.x; s[row][c4 + 1] = v.y;
        s[row][c4 + 2] = v.z; s[row][c4 + 3] = v.w;
    }
    __syncthreads();

    const int NP = N / 16;   // pairs per row
    uint4* dst = wf + (((size_t)e * (K / 16) + kt) * NP + nb * 8) * 32;
    {
        int k2 = tid & 3, c8 = (tid >> 2) & 7, P = tid >> 5;
        int n = P * 16 + c8;
        uint4 v;
        v.x = pack2(s[2 * k2][n],         s[2 * k2 + 1][n]);
        v.y = pack2(s[2 * k2 + 8][n],     s[2 * k2 + 9][n]);
        v.z = pack2(s[2 * k2][n + 8],     s[2 * k2 + 1][n + 8]);
        v.w = pack2(s[2 * k2 + 8][n + 8], s[2 * k2 + 9][n + 8]);
        dst[(size_t)P * 32 + (tid & 31)] = v;
    }
}

// =====================================================================================
// FFN GEMMs: 4 warps/CTA (2 wm x 2 wn of 64x64 tiles), CTA 128x128, k-step 16, fp16 MMA.
// NO smem, NO barriers. 3-stage register pipeline; A: 4x LDG.128, B: 4x LDG.128 (paired).
// =====================================================================================

// ---------------- kernel 3: grouped GEMM1: g_hf = frag16(gelu(A @ wf1 + b1)) ----------------
__global__ __launch_bounds__(128, 2) void ffn1_kernel(const float* __restrict__ b1, int e0)
{
    const int e  = e0 + blockIdx.z;
    const int me = g_cnt[e];
    const int mt = blockIdx.x;
    if (mt * BM >= me) return;
    const int n0 = blockIdx.y * BN;

    const int tid  = threadIdx.x;
    const int lane = tid & 31;
    const int wid  = tid >> 5;
    const int wm   = wid >> 1;
    const int wn   = wid & 1;
    const int g    = lane >> 2;
    const int t    = lane & 3;

    const uint4* aF = (const uint4*)g_af;
    const size_t aB = (size_t)(e * 32 + mt) * 64 * 256 + (wm * 4) * 32 + lane;
    // paired B: NP = HID/16 = 256 -> per kt stride = 256*32 = 8192 uint4
    const uint4* bW = g_wf1 + (size_t)e * 64 * 256 * 32
                    + ((size_t)(n0 >> 4) + wn * 4) * 32 + lane;

    float acc[4][8][4];
#pragma unroll
    for (int a = 0; a < 4; a++)
#pragma unroll
        for (int b = 0; b < 8; b++)
#pragma unroll
            for (int q = 0; q < 4; q++) acc[a][b][q] = 0.f;

    uint4 ab[3][4];
    uint4 bb[3][4];

    // prime stages 0,1
#pragma unroll
    for (int s = 0; s < 2; s++) {
#pragma unroll
        for (int mi = 0; mi < 4; mi++)
            ab[s][mi] = aF[aB + (size_t)s * 256 + mi * 32];
#pragma unroll
        for (int p = 0; p < 4; p++)
            bb[s][p] = bW[(size_t)s * 8192 + p * 32];
    }

    const int KT = DIM / 16;   // 64
#pragma unroll
    for (int kt = 0; kt < KT; kt++) {
        const int cur = kt % 3;
        if (kt + 2 < KT) {
            const int nx = (kt + 2) % 3;
#pragma unroll
            for (int mi = 0; mi < 4; mi++)
                ab[nx][mi] = aF[aB + (size_t)(kt + 2) * 256 + mi * 32];
#pragma unroll
            for (int p = 0; p < 4; p++)
                bb[nx][p] = bW[(size_t)(kt + 2) * 8192 + p * 32];
        }
#pragma unroll
        for (int p = 0; p < 4; p++) {
#pragma unroll
            for (int mi = 0; mi < 4; mi++)
                mma16(acc[mi][2 * p], ab[cur][mi], bb[cur][p].x, bb[cur][p].y);
#pragma unroll
            for (int mi = 0; mi < 4; mi++)
                mma16(acc[mi][2 * p + 1], ab[cur][mi], bb[cur][p].z, bb[cur][p].w);
        }
    }

    // epilogue: +b1, exact GELU, pack to fp16 fragment layout for GEMM2
    float bv[8][2];
#pragma unroll
    for (int ni = 0; ni < 8; ni++) {
        int c = n0 + wn * 64 + ni * 8 + 2 * t;
        bv[ni][0] = b1[e * HID + c];
        bv[ni][1] = b1[e * HID + c + 1];
    }
    uint4* hf = (uint4*)g_hf;
#pragma unroll
    for (int mi = 0; mi < 4; mi++) {
#pragma unroll
        for (int p = 0; p < 4; p++) {
            int n0i = 2 * p, n1i = 2 * p + 1;
            uint4 v;
            v.x = pack2(gelu_exact(acc[mi][n0i][0] + bv[n0i][0]),
                        gelu_exact(acc[mi][n0i][1] + bv[n0i][1]));
            v.y = pack2(gelu_exact(acc[mi][n0i][2] + bv[n0i][0]),
                        gelu_exact(acc[mi][n0i][3] + bv[n0i][1]));
            v.z = pack2(gelu_exact(acc[mi][n1i][0] + bv[n1i][0]),
                        gelu_exact(acc[mi][n1i][1] + bv[n1i][1]));
            v.w = pack2(gelu_exact(acc[mi][n1i][2] + bv[n1i][0]),
                        gelu_exact(acc[mi][n1i][3] + bv[n1i][1]));
            int kq = (n0 >> 4) + wn * 4 + p;
            hf[(((size_t)(e * 32 + mt) * 256 + kq) * 8 + (wm * 4 + mi)) * 32 + lane] = v;
        }
    }
}

// ---------------- kernel 4: grouped GEMM2 (K-split x2): out[tok] += c * (g_hf @ wf2) ----------------
__global__ __launch_bounds__(128, 2) void ffn2_kernel(float* __restrict__ out, int e0)
{
    const int e  = e0 + (blockIdx.z >> 1);
    const int sp = blockIdx.z & 1;
    const int me = g_cnt[e];
    const int mt = blockIdx.x;
    if (mt * BM >= me) return;
    const int n0 = blockIdx.y * BN;

    const int tid  = threadIdx.x;
    const int lane = tid & 31;
    const int wid  = tid >> 5;
    const int wm   = wid >> 1;
    const int wn   = wid & 1;
    const int g    = lane >> 2;
    const int t    = lane & 3;

    const uint4* aF = (const uint4*)g_hf;
    const size_t aB = (size_t)(e * 32 + mt) * 256 * 256 + (size_t)(sp * 128) * 256
                    + (wm * 4) * 32 + lane;
    // paired B: NP = DIM/16 = 64 -> per kt stride = 64*32 = 2048 uint4
    const uint4* bW = g_wf2 + (size_t)e * 256 * 64 * 32 + (size_t)(sp * 128) * 2048
                    + ((size_t)(n0 >> 4) + wn * 4) * 32 + lane;

    float acc[4][8][4];
#pragma unroll
    for (int a = 0; a < 4; a++)
#pragma unroll
        for (int b = 0; b < 8; b++)
#pragma unroll
            for (int q = 0; q < 4; q++) acc[a][b][q] = 0.f;

    uint4 ab[3][4];
    uint4 bb[3][4];

#pragma unroll
    for (int s = 0; s < 2; s++) {
#pragma unroll
        for (int mi = 0; mi < 4; mi++)
            ab[s][mi] = aF[aB + (size_t)s * 256 + mi * 32];
#pragma unroll
        for (int p = 0; p < 4; p++)
            bb[s][p] = bW[(size_t)s * 2048 + p * 32];
    }

    const int KT = (HID / 2) / 16;   // 128 per split
#pragma unroll
    for (int kt = 0; kt < KT; kt++) {
        const int cur = kt % 3;
        if (kt + 2 < KT) {
            const int nx = (kt + 2) % 3;
#pragma unroll
            for (int mi = 0; mi < 4; mi++)
                ab[nx][mi] = aF[aB + (size_t)(kt + 2) * 256 + mi * 32];
#pragma unroll
            for (int p = 0; p < 4; p++)
                bb[nx][p] = bW[(size_t)(kt + 2) * 2048 + p * 32];
        }
#pragma unroll
        for (int p = 0; p < 4; p++) {
#pragma unroll
            for (int mi = 0; mi < 4; mi++)
                mma16(acc[mi][2 * p], ab[cur][mi], bb[cur][p].x, bb[cur][p].y);
#pragma unroll
            for (int mi = 0; mi < 4; mi++)
                mma16(acc[mi][2 * p + 1], ab[cur][mi], bb[cur][p].z, bb[cur][p].w);
        }
    }

    // epilogue: scaled vector scatter-add (red.global.add.v2.f32); split partials add
#pragma unroll
    for (int mi = 0; mi < 4; mi++) {
#pragma unroll
        for (int h2 = 0; h2 < 2; h2++) {
            int row = wm * 64 + mi * 16 + g + 8 * h2;
            int ss = mt * BM + row;
            if (ss < me) {
                int tok  = g_idx[e][ss];
                float wc = g_wt[e][ss];
                float* orow = out + (size_t)tok * DIM;
#pragma unroll
                for (int ni = 0; ni < 8; ni++) {
                    int col = n0 + wn * 64 + ni * 8 + 2 * t;
                    red_add_v2(orow + col,
                               wc * acc[mi][ni][2 * h2 + 0],
                               wc * acc[mi][ni][2 * h2 + 1]);
                }
            }
        }
    }
}

// ---------------- launch ----------------
extern "C" void kernel_launch(void* const* d_in, const int* in_sizes, int n_in,
                              void* d_out, int out_size)
{
    (void)in_sizes; (void)n_in; (void)out_size;
    const float* x  = (const float*)d_in[0];
    const float* ei = (const float*)d_in[1];
    const float* wg = (const float*)d_in[2];
    const float* bg = (const float*)d_in[3];
    const float* w1 = (const float*)d_in[4];
    const float* b1 = (const float*)d_in[5];
    const float* w2 = (const float*)d_in[6];
    const float* b2 = (const float*)d_in[7];
    float* out = (float*)d_out;

    uint4* wf1; cudaGetSymbolAddress((void**)&wf1, g_wf1);
    uint4* wf2; cudaGetSymbolAddress((void**)&wf2, g_wf2);

    // lazily-created single side stream + events (same resource budget that passed
    // the allocation guard in prior rounds; captured work identical every call)
    static cudaStream_t s_aux = nullptr;
    static cudaEvent_t ev_fork = nullptr, ev_w1 = nullptr, ev_w2 = nullptr;
    static cudaEvent_t ev_compact = nullptr, ev_done = nullptr;
    if (!s_aux) {
        cudaStreamCreateWithFlags(&s_aux, cudaStreamNonBlocking);
        cudaEventCreateWithFlags(&ev_fork, cudaEventDisableTiming);
        cudaEventCreateWithFlags(&ev_w1, cudaEventDisableTiming);
        cudaEventCreateWithFlags(&ev_w2, cudaEventDisableTiming);
        cudaEventCreateWithFlags(&ev_compact, cudaEventDisableTiming);
        cudaEventCreateWithFlags(&ev_done, cudaEventDisableTiming);
    }

    // fork: weight permutation first on the side stream
    cudaEventRecord(ev_fork, 0);
    cudaStreamWaitEvent(s_aux, ev_fork, 0);
    permW_kernel<<<dim3(DIM / 16, HID / 128, NEXP), 256, 0, s_aux>>>(w1, wf1, DIM, HID);
    cudaEventRecord(ev_w1, s_aux);
    permW_kernel<<<dim3(HID / 16, DIM / 128, NEXP), 256, 0, s_aux>>>(w2, wf2, HID, DIM);
    cudaEventRecord(ev_w2, s_aux);

    // gate chain on origin stream
    gate_kernel<<<NTOK / 8, 256>>>(x, wg, bg, b2, out);
    compact_kernel<<<NEXP, 256>>>();
    cudaEventRecord(ev_compact, 0);

    // pipeline A (experts 0..3) on origin stream
    permA_kernel<<<dim3(NTOK / BM, 4), 256>>>(ei, 0);
    cudaStreamWaitEvent(0, ev_w1, 0);
    ffn1_kernel<<<dim3(NTOK / BM, HID / BN, 4), 128>>>(b1, 0);
    cudaStreamWaitEvent(0, ev_w2, 0);
    ffn2_kernel<<<dim3(NTOK / BM, DIM / BN, 8), 128>>>(out, 0);

    // pipeline B (experts 4..7) on side stream (already ordered after permW1/permW2)
    cudaStreamWaitEvent(s_aux, ev_compact, 0);
    permA_kernel<<<dim3(NTOK / BM, 4), 256, 0, s_aux>>>(ei, 4);
    ffn1_kernel<<<dim3(NTOK / BM, HID / BN, 4), 128, 0, s_aux>>>(b1, 4);
    ffn2_kernel<<<dim3(NTOK / BM, DIM / BN, 8), 128, 0, s_aux>>>(out, 4);
    cudaEventRecord(ev_done, s_aux);

    // join
    cudaStreamWaitEvent(0, ev_done, 0);
}